// round 1
// baseline (speedup 1.0000x reference)
#include <cuda_runtime.h>

typedef unsigned long long u64;

static constexpr int BT     = 64;    // batch tile per block
static constexpr int NTHR   = 512;   // 64 batch x 8 output-groups
static constexpr int T_HIST = 11;
static constexpr int T_PRED = 80;
static constexpr int BATCH  = 8192;

// ---- shared memory layout (float offsets) ----
static constexpr int S_H1   = 0;        // 2 buffers x 64 x 65
static constexpr int S_H2   = 8320;     // 2 buffers x 64 x 65
static constexpr int S_WT0  = 16640;    // Whh0^T  [k][j] 64x64
static constexpr int S_WT1  = 20736;    // Wih1^T  [k][j] 64x64
static constexpr int S_WT2  = 24832;    // Whh1^T  [k][j] 64x64
static constexpr int S_WX0  = 28928;    // Wih0[:,0]  (64)
static constexpr int S_WX1  = 28992;    // Wih0[:,1]  (64)
static constexpr int S_B0   = 29056;    // bih0+bhh0  (64)
static constexpr int S_B1   = 29120;    // bih1+bhh1  (64)
static constexpr int S_FCW0 = 29184;    // fc_W row0  (64)
static constexpr int S_FCW1 = 29248;    // fc_W row1  (64)
static constexpr int S_FCB  = 29312;    // fc_b (2)
static constexpr int S_X    = 29328;    // 64 x 22
static constexpr int S_PRED = 30736;    // 64 x 2
static constexpr int S_PART = 30864;    // 8 x 64 x 2
static constexpr int S_TOTAL= 31888;    // floats -> 127,552 bytes

// ---- packed f32x2 helpers (FFMA2 only reachable via PTX on sm_103a) ----
__device__ __forceinline__ u64 dup2(float x) {
    u64 r; asm("mov.b64 %0, {%1, %1};" : "=l"(r) : "f"(x)); return r;
}
__device__ __forceinline__ u64 fma2(u64 a, u64 b, u64 c) {
    u64 d; asm("fma.rn.f32x2 %0, %1, %2, %3;" : "=l"(d) : "l"(a), "l"(b), "l"(c)); return d;
}
__device__ __forceinline__ void unpk(u64 v, float& lo, float& hi) {
    asm("mov.b64 {%0, %1}, %2;" : "=f"(lo), "=f"(hi) : "l"(v));
}

__device__ __forceinline__ void tanh8(const u64 c[4], float r[8]) {
#pragma unroll
    for (int i = 0; i < 4; ++i) {
        float lo, hi; unpk(c[i], lo, hi);
        r[2*i]   = tanhf(lo);
        r[2*i+1] = tanhf(hi);
    }
}

// acc += h_row @ WT  (WT pre-offset by j0; [k][j] layout, LDS.128 broadcast)
__device__ __forceinline__ void gemm1(u64 c[4], const float* __restrict__ h,
                                      const float* __restrict__ wt) {
#pragma unroll 8
    for (int k = 0; k < 64; ++k) {
        u64 aa = dup2(h[k]);
        ulonglong2 w0 = *reinterpret_cast<const ulonglong2*>(wt + k*64);
        ulonglong2 w1 = *reinterpret_cast<const ulonglong2*>(wt + k*64 + 4);
        c[0] = fma2(aa, w0.x, c[0]); c[1] = fma2(aa, w0.y, c[1]);
        c[2] = fma2(aa, w1.x, c[2]); c[3] = fma2(aa, w1.y, c[3]);
    }
}

// acc += ha @ WA + hb @ WB  (fused k-loop for layer 1)
__device__ __forceinline__ void gemm2(u64 c[4],
                                      const float* __restrict__ ha, const float* __restrict__ wa,
                                      const float* __restrict__ hb, const float* __restrict__ wb) {
#pragma unroll 8
    for (int k = 0; k < 64; ++k) {
        u64 aa = dup2(ha[k]);
        u64 bb = dup2(hb[k]);
        ulonglong2 wa0 = *reinterpret_cast<const ulonglong2*>(wa + k*64);
        ulonglong2 wa1 = *reinterpret_cast<const ulonglong2*>(wa + k*64 + 4);
        ulonglong2 wb0 = *reinterpret_cast<const ulonglong2*>(wb + k*64);
        ulonglong2 wb1 = *reinterpret_cast<const ulonglong2*>(wb + k*64 + 4);
        c[0] = fma2(aa, wa0.x, c[0]); c[1] = fma2(aa, wa0.y, c[1]);
        c[2] = fma2(aa, wa1.x, c[2]); c[3] = fma2(aa, wa1.y, c[3]);
        c[0] = fma2(bb, wb0.x, c[0]); c[1] = fma2(bb, wb0.y, c[1]);
        c[2] = fma2(bb, wb1.x, c[2]); c[3] = fma2(bb, wb1.y, c[3]);
    }
}

// acc = b0 + x0*wx0 + x1*wx1  (layer-0 bias + 2-dim input injection)
__device__ __forceinline__ void init_l0(u64 c[4], const float* __restrict__ sm,
                                        int j0, float x0, float x1) {
    const ulonglong2* bp = reinterpret_cast<const ulonglong2*>(sm + S_B0 + j0);
    ulonglong2 b01 = bp[0], b23 = bp[1];
    c[0] = b01.x; c[1] = b01.y; c[2] = b23.x; c[3] = b23.y;
    u64 xa = dup2(x0), xb = dup2(x1);
    const ulonglong2* wa = reinterpret_cast<const ulonglong2*>(sm + S_WX0 + j0);
    const ulonglong2* wb = reinterpret_cast<const ulonglong2*>(sm + S_WX1 + j0);
    ulonglong2 wa0 = wa[0], wa1 = wa[1], wb0 = wb[0], wb1 = wb[1];
    c[0] = fma2(xa, wa0.x, c[0]); c[1] = fma2(xa, wa0.y, c[1]);
    c[2] = fma2(xa, wa1.x, c[2]); c[3] = fma2(xa, wa1.y, c[3]);
    c[0] = fma2(xb, wb0.x, c[0]); c[1] = fma2(xb, wb0.y, c[1]);
    c[2] = fma2(xb, wb1.x, c[2]); c[3] = fma2(xb, wb1.y, c[3]);
}

__device__ __forceinline__ void init_b1(u64 c[4], const float* __restrict__ sm, int j0) {
    const ulonglong2* bp = reinterpret_cast<const ulonglong2*>(sm + S_B1 + j0);
    ulonglong2 a = bp[0], b = bp[1];
    c[0] = a.x; c[1] = a.y; c[2] = b.x; c[3] = b.y;
}

// Load one phase's weights (transposed) + combined biases into SMEM.
__device__ __forceinline__ void load_phase(float* sm,
    const float* __restrict__ Wih0, const float* __restrict__ Whh0,
    const float* __restrict__ bih0, const float* __restrict__ bhh0,
    const float* __restrict__ Wih1, const float* __restrict__ Whh1,
    const float* __restrict__ bih1, const float* __restrict__ bhh1, int tid) {
    for (int idx = tid; idx < 4096; idx += NTHR) {
        int j = idx & 63, k = idx >> 6;   // dst idx = k*64 + j  (conflict-free STS)
        sm[S_WT0 + idx] = Whh0[j*64 + k];
        sm[S_WT1 + idx] = Wih1[j*64 + k];
        sm[S_WT2 + idx] = Whh1[j*64 + k];
    }
    if (tid < 64) {
        sm[S_WX0 + tid] = Wih0[tid*2];
        sm[S_WX1 + tid] = Wih0[tid*2 + 1];
        sm[S_B0 + tid]  = bih0[tid] + bhh0[tid];
        sm[S_B1 + tid]  = bih1[tid] + bhh1[tid];
    }
}

__global__ __launch_bounds__(NTHR, 1)
void rnn_seq2seq_kernel(const float* __restrict__ x,
    const float* __restrict__ eWih0, const float* __restrict__ eWhh0,
    const float* __restrict__ ebih0, const float* __restrict__ ebhh0,
    const float* __restrict__ eWih1, const float* __restrict__ eWhh1,
    const float* __restrict__ ebih1, const float* __restrict__ ebhh1,
    const float* __restrict__ dWih0, const float* __restrict__ dWhh0,
    const float* __restrict__ dbih0, const float* __restrict__ dbhh0,
    const float* __restrict__ dWih1, const float* __restrict__ dWhh1,
    const float* __restrict__ dbih1, const float* __restrict__ dbhh1,
    const float* __restrict__ fcW, const float* __restrict__ fcb,
    float* __restrict__ out)
{
    extern __shared__ float sm[];
    const int tid = threadIdx.x;
    const int b   = tid & 63;      // batch row within tile (lanes = consecutive b)
    const int jg  = tid >> 6;      // output group
    const int j0  = jg * 8;
    const int bg0 = blockIdx.x * BT;

    // zero hidden state buffers
    for (int i = tid; i < 16640; i += NTHR) sm[i] = 0.f;
    // stage x tile (64 x 22 floats)
    for (int i = tid; i < BT * 2 * T_HIST; i += NTHR)
        sm[S_X + i] = x[(size_t)bg0 * (2*T_HIST) + i];
    if (tid < 64) { sm[S_FCW0 + tid] = fcW[tid]; sm[S_FCW1 + tid] = fcW[64 + tid]; }
    if (tid < 2)  { sm[S_FCB + tid] = fcb[tid]; }
    load_phase(sm, eWih0, eWhh0, ebih0, ebhh0, eWih1, eWhh1, ebih1, ebhh1, tid);
    __syncthreads();

    int cur = 0;

    // ================= encoder: 11 steps, layers interleaved =================
    for (int t = 0; t < T_HIST; ++t) {
        const float* h1c = sm + S_H1 + cur*4160 + b*65;
        const float* h2c = sm + S_H2 + cur*4160 + b*65;
        float* h1n = sm + S_H1 + (cur^1)*4160 + b*65;
        float* h2n = sm + S_H2 + (cur^1)*4160 + b*65;

        float x0 = sm[S_X + b*22 + 2*t];
        float x1 = sm[S_X + b*22 + 2*t + 1];

        u64 c[4];
        init_l0(c, sm, j0, x0, x1);
        gemm1(c, h1c, sm + S_WT0 + j0);
        float r1[8]; tanh8(c, r1);
#pragma unroll
        for (int i = 0; i < 8; ++i) h1n[j0 + i] = r1[i];
        __syncthreads();

        u64 c2[4];
        init_b1(c2, sm, j0);
        gemm2(c2, h1n, sm + S_WT1 + j0, h2c, sm + S_WT2 + j0);
        float r2[8]; tanh8(c2, r2);
#pragma unroll
        for (int i = 0; i < 8; ++i) h2n[j0 + i] = r2[i];
        __syncthreads();
        cur ^= 1;
    }

    // ================= swap in decoder weights =================
    load_phase(sm, dWih0, dWhh0, dbih0, dbhh0, dWih1, dWhh1, dbih1, dbhh1, tid);
    if (tid < 64) {  // first decoder input = x[:, -1, :]
        sm[S_PRED + tid*2]     = sm[S_X + tid*22 + 2*(T_HIST-1)];
        sm[S_PRED + tid*2 + 1] = sm[S_X + tid*22 + 2*(T_HIST-1) + 1];
    }
    __syncthreads();

    // ================= decoder: 80 steps, autoregressive =================
    for (int t = 0; t < T_PRED; ++t) {
        const float* h1c = sm + S_H1 + cur*4160 + b*65;
        const float* h2c = sm + S_H2 + cur*4160 + b*65;
        float* h1n = sm + S_H1 + (cur^1)*4160 + b*65;
        float* h2n = sm + S_H2 + (cur^1)*4160 + b*65;

        float p0 = sm[S_PRED + b*2];
        float p1 = sm[S_PRED + b*2 + 1];

        u64 c[4];
        init_l0(c, sm, j0, p0, p1);
        gemm1(c, h1c, sm + S_WT0 + j0);
        float r1[8]; tanh8(c, r1);
#pragma unroll
        for (int i = 0; i < 8; ++i) h1n[j0 + i] = r1[i];
        __syncthreads();

        u64 c2[4];
        init_b1(c2, sm, j0);
        gemm2(c2, h1n, sm + S_WT1 + j0, h2c, sm + S_WT2 + j0);
        float r2[8]; tanh8(c2, r2);

        // fc partials from registers + h2 writeback
        float q0 = 0.f, q1 = 0.f;
#pragma unroll
        for (int i = 0; i < 8; ++i) {
            q0 += r2[i] * sm[S_FCW0 + j0 + i];
            q1 += r2[i] * sm[S_FCW1 + j0 + i];
            h2n[j0 + i] = r2[i];
        }
        sm[S_PART + jg*128 + b*2]     = q0;
        sm[S_PART + jg*128 + b*2 + 1] = q1;
        __syncthreads();

        if (tid < 64) {  // reduce 8 partials -> pred, feed back + emit
            float s0 = sm[S_FCB], s1 = sm[S_FCB + 1];
#pragma unroll
            for (int g = 0; g < 8; ++g) {
                s0 += sm[S_PART + g*128 + tid*2];
                s1 += sm[S_PART + g*128 + tid*2 + 1];
            }
            sm[S_PRED + tid*2]     = s0;
            sm[S_PRED + tid*2 + 1] = s1;
            float* op = out + (size_t)(bg0 + tid) * (T_PRED*2) + t*2;
            op[0] = s0; op[1] = s1;
        }
        __syncthreads();
        cur ^= 1;
    }
}

extern "C" void kernel_launch(void* const* d_in, const int* in_sizes, int n_in,
                              void* d_out, int out_size) {
    (void)in_sizes; (void)n_in; (void)out_size;
    const size_t smem = S_TOTAL * sizeof(float);
    cudaFuncSetAttribute(rnn_seq2seq_kernel,
                         cudaFuncAttributeMaxDynamicSharedMemorySize, (int)smem);
    rnn_seq2seq_kernel<<<BATCH / BT, NTHR, smem>>>(
        (const float*)d_in[0],
        (const float*)d_in[1],  (const float*)d_in[2],  (const float*)d_in[3],  (const float*)d_in[4],
        (const float*)d_in[5],  (const float*)d_in[6],  (const float*)d_in[7],  (const float*)d_in[8],
        (const float*)d_in[9],  (const float*)d_in[10], (const float*)d_in[11], (const float*)d_in[12],
        (const float*)d_in[13], (const float*)d_in[14], (const float*)d_in[15], (const float*)d_in[16],
        (const float*)d_in[17], (const float*)d_in[18],
        (float*)d_out);
}

// round 2
// speedup vs baseline: 1.4518x; 1.4518x over previous
#include <cuda_runtime.h>

typedef unsigned long long u64;

static constexpr int NTHR   = 256;   // 32 b-slots x 8 output-groups
static constexpr int BT     = 64;    // batch rows per block (2 per thread)
static constexpr int T_HIST = 11;
static constexpr int T_PRED = 80;
static constexpr int BATCH  = 8192;

// ---- shared memory layout (float offsets) ----
static constexpr int HSTR   = 68;       // h row stride (conflict-free LDS.128)
static constexpr int HBUF   = 64 * HSTR;        // 4352 floats per buffer
static constexpr int S_H1   = 0;                // 2 buffers
static constexpr int S_H2   = 2 * HBUF;         // 8704
static constexpr int S_WT0  = 4 * HBUF;         // 17408: Whh0^T [k][j]
static constexpr int S_WT1  = S_WT0 + 4096;     // Wih1^T
static constexpr int S_WT2  = S_WT1 + 4096;     // Whh1^T
static constexpr int S_WX0  = S_WT2 + 4096;     // Wih0[:,0]
static constexpr int S_WX1  = S_WX0 + 64;
static constexpr int S_B0   = S_WX1 + 64;       // bih0+bhh0
static constexpr int S_B1   = S_B0 + 64;        // bih1+bhh1
static constexpr int S_FCW0 = S_B1 + 64;
static constexpr int S_FCW1 = S_FCW0 + 64;
static constexpr int S_FCB  = S_FCW1 + 64;      // 4 (2 used)
static constexpr int S_X    = S_FCB + 4;        // 64 x 22
static constexpr int S_PART = S_X + 64 * 22;    // 8 x 64 x 2
static constexpr int S_TOTAL= S_PART + 8 * 64 * 2;   // 32516 floats = 130,064 B

// ---- packed f32x2 helpers ----
__device__ __forceinline__ u64 dup2(float x) {
    u64 r; asm("mov.b64 %0, {%1, %1};" : "=l"(r) : "f"(x)); return r;
}
__device__ __forceinline__ u64 fma2(u64 a, u64 b, u64 c) {
    u64 d; asm("fma.rn.f32x2 %0, %1, %2, %3;" : "=l"(d) : "l"(a), "l"(b), "l"(c)); return d;
}
__device__ __forceinline__ void unpk(u64 v, float& lo, float& hi) {
    asm("mov.b64 {%0, %1}, %2;" : "=f"(lo), "=f"(hi) : "l"(v));
}

__device__ __forceinline__ float tanh_fast(float x) {
    float t = __expf(2.0f * x);
    return 1.0f - __fdividef(2.0f, t + 1.0f);
}
__device__ __forceinline__ void tanh8(const u64 c[4], float r[8]) {
#pragma unroll
    for (int i = 0; i < 4; ++i) {
        float lo, hi; unpk(c[i], lo, hi);
        r[2*i]   = tanh_fast(lo);
        r[2*i+1] = tanh_fast(hi);
    }
}

// acc(2 rows) += h_row @ WT   (WT pre-offset by j0, [k][j] layout; h via float4)
__device__ __forceinline__ void gemv1_r2(u64 ca[4], u64 cb[4],
    const float* __restrict__ ha, const float* __restrict__ hb,
    const float* __restrict__ wt) {
#pragma unroll 4
    for (int q = 0; q < 16; ++q) {
        float4 va = *reinterpret_cast<const float4*>(ha + 4*q);
        float4 vb = *reinterpret_cast<const float4*>(hb + 4*q);
        const float* wr = wt + 4*q*64;
        const float fa[4] = {va.x, va.y, va.z, va.w};
        const float fb[4] = {vb.x, vb.y, vb.z, vb.w};
#pragma unroll
        for (int kk = 0; kk < 4; ++kk) {
            ulonglong2 w0 = *reinterpret_cast<const ulonglong2*>(wr + kk*64);
            ulonglong2 w1 = *reinterpret_cast<const ulonglong2*>(wr + kk*64 + 4);
            u64 aa = dup2(fa[kk]);
            u64 bb = dup2(fb[kk]);
            ca[0] = fma2(aa, w0.x, ca[0]); ca[1] = fma2(aa, w0.y, ca[1]);
            ca[2] = fma2(aa, w1.x, ca[2]); ca[3] = fma2(aa, w1.y, ca[3]);
            cb[0] = fma2(bb, w0.x, cb[0]); cb[1] = fma2(bb, w0.y, cb[1]);
            cb[2] = fma2(bb, w1.x, cb[2]); cb[3] = fma2(bb, w1.y, cb[3]);
        }
    }
}

// acc(2 rows) += h1 @ W1 + h2 @ W2   (fused k-loop, layer 1)
__device__ __forceinline__ void gemv2_r2(u64 ca[4], u64 cb[4],
    const float* __restrict__ h1a, const float* __restrict__ h1b,
    const float* __restrict__ w1,
    const float* __restrict__ h2a, const float* __restrict__ h2b,
    const float* __restrict__ w2) {
#pragma unroll 2
    for (int q = 0; q < 16; ++q) {
        float4 v1a = *reinterpret_cast<const float4*>(h1a + 4*q);
        float4 v1b = *reinterpret_cast<const float4*>(h1b + 4*q);
        float4 v2a = *reinterpret_cast<const float4*>(h2a + 4*q);
        float4 v2b = *reinterpret_cast<const float4*>(h2b + 4*q);
        const float* wr1 = w1 + 4*q*64;
        const float* wr2 = w2 + 4*q*64;
        const float f1a[4] = {v1a.x, v1a.y, v1a.z, v1a.w};
        const float f1b[4] = {v1b.x, v1b.y, v1b.z, v1b.w};
        const float f2a[4] = {v2a.x, v2a.y, v2a.z, v2a.w};
        const float f2b[4] = {v2b.x, v2b.y, v2b.z, v2b.w};
#pragma unroll
        for (int kk = 0; kk < 4; ++kk) {
            ulonglong2 u0 = *reinterpret_cast<const ulonglong2*>(wr1 + kk*64);
            ulonglong2 u1 = *reinterpret_cast<const ulonglong2*>(wr1 + kk*64 + 4);
            ulonglong2 v0 = *reinterpret_cast<const ulonglong2*>(wr2 + kk*64);
            ulonglong2 v1 = *reinterpret_cast<const ulonglong2*>(wr2 + kk*64 + 4);
            u64 a1 = dup2(f1a[kk]);
            u64 b1 = dup2(f1b[kk]);
            u64 a2 = dup2(f2a[kk]);
            u64 b2 = dup2(f2b[kk]);
            ca[0] = fma2(a1, u0.x, ca[0]); ca[1] = fma2(a1, u0.y, ca[1]);
            ca[2] = fma2(a1, u1.x, ca[2]); ca[3] = fma2(a1, u1.y, ca[3]);
            cb[0] = fma2(b1, u0.x, cb[0]); cb[1] = fma2(b1, u0.y, cb[1]);
            cb[2] = fma2(b1, u1.x, cb[2]); cb[3] = fma2(b1, u1.y, cb[3]);
            ca[0] = fma2(a2, v0.x, ca[0]); ca[1] = fma2(a2, v0.y, ca[1]);
            ca[2] = fma2(a2, v1.x, ca[2]); ca[3] = fma2(a2, v1.y, ca[3]);
            cb[0] = fma2(b2, v0.x, cb[0]); cb[1] = fma2(b2, v0.y, cb[1]);
            cb[2] = fma2(b2, v1.x, cb[2]); cb[3] = fma2(b2, v1.y, cb[3]);
        }
    }
}

// c = B0 + x0*WX0 + x1*WX1 over j-slice
__device__ __forceinline__ void init_l0(u64 c[4], const float* __restrict__ sm,
                                        int j0, float x0, float x1) {
    const ulonglong2* bp = reinterpret_cast<const ulonglong2*>(sm + S_B0 + j0);
    ulonglong2 b01 = bp[0], b23 = bp[1];
    c[0] = b01.x; c[1] = b01.y; c[2] = b23.x; c[3] = b23.y;
    u64 xa = dup2(x0), xb = dup2(x1);
    const ulonglong2* wa = reinterpret_cast<const ulonglong2*>(sm + S_WX0 + j0);
    const ulonglong2* wb = reinterpret_cast<const ulonglong2*>(sm + S_WX1 + j0);
    ulonglong2 wa0 = wa[0], wa1 = wa[1], wb0 = wb[0], wb1 = wb[1];
    c[0] = fma2(xa, wa0.x, c[0]); c[1] = fma2(xa, wa0.y, c[1]);
    c[2] = fma2(xa, wa1.x, c[2]); c[3] = fma2(xa, wa1.y, c[3]);
    c[0] = fma2(xb, wb0.x, c[0]); c[1] = fma2(xb, wb0.y, c[1]);
    c[2] = fma2(xb, wb1.x, c[2]); c[3] = fma2(xb, wb1.y, c[3]);
}
__device__ __forceinline__ void init_b1(u64 c[4], const float* __restrict__ sm, int j0) {
    const ulonglong2* bp = reinterpret_cast<const ulonglong2*>(sm + S_B1 + j0);
    ulonglong2 a = bp[0], b = bp[1];
    c[0] = a.x; c[1] = a.y; c[2] = b.x; c[3] = b.y;
}

__device__ __forceinline__ void load_phase(float* sm,
    const float* __restrict__ Wih0, const float* __restrict__ Whh0,
    const float* __restrict__ bih0, const float* __restrict__ bhh0,
    const float* __restrict__ Wih1, const float* __restrict__ Whh1,
    const float* __restrict__ bih1, const float* __restrict__ bhh1, int tid) {
    for (int idx = tid; idx < 4096; idx += NTHR) {
        int j = idx & 63, k = idx >> 6;   // dst idx = k*64 + j (conflict-free STS)
        sm[S_WT0 + idx] = Whh0[j*64 + k];
        sm[S_WT1 + idx] = Wih1[j*64 + k];
        sm[S_WT2 + idx] = Whh1[j*64 + k];
    }
    if (tid < 64) {
        sm[S_WX0 + tid] = Wih0[tid*2];
        sm[S_WX1 + tid] = Wih0[tid*2 + 1];
        sm[S_B0 + tid]  = bih0[tid] + bhh0[tid];
        sm[S_B1 + tid]  = bih1[tid] + bhh1[tid];
    }
}

__global__ __launch_bounds__(NTHR, 1)
void rnn_seq2seq_kernel(const float* __restrict__ x,
    const float* __restrict__ eWih0, const float* __restrict__ eWhh0,
    const float* __restrict__ ebih0, const float* __restrict__ ebhh0,
    const float* __restrict__ eWih1, const float* __restrict__ eWhh1,
    const float* __restrict__ ebih1, const float* __restrict__ ebhh1,
    const float* __restrict__ dWih0, const float* __restrict__ dWhh0,
    const float* __restrict__ dbih0, const float* __restrict__ dbhh0,
    const float* __restrict__ dWih1, const float* __restrict__ dWhh1,
    const float* __restrict__ dbih1, const float* __restrict__ dbhh1,
    const float* __restrict__ fcW, const float* __restrict__ fcb,
    float* __restrict__ out)
{
    extern __shared__ float sm[];
    const int tid = threadIdx.x;
    const int bs  = tid & 31;      // batch slot (rows bs and bs+32)
    const int jg  = tid >> 5;      // output group 0..7
    const int j0  = jg * 8;
    const int bg0 = blockIdx.x * BT;

    // zero buffer 0 of both layers
    for (int i = tid; i < HBUF; i += NTHR) {
        sm[S_H1 + i] = 0.f;
        sm[S_H2 + i] = 0.f;
    }
    // stage x tile (64 x 22)
    for (int i = tid; i < BT * 2 * T_HIST; i += NTHR)
        sm[S_X + i] = x[(size_t)bg0 * (2*T_HIST) + i];
    if (tid < 64) { sm[S_FCW0 + tid] = fcW[tid]; sm[S_FCW1 + tid] = fcW[64 + tid]; }
    if (tid < 2)  { sm[S_FCB + tid] = fcb[tid]; }
    load_phase(sm, eWih0, eWhh0, ebih0, ebhh0, eWih1, eWhh1, ebih1, ebhh1, tid);
    __syncthreads();

    int cur = 0;
    const int rowA = bs * HSTR;
    const int rowB = (bs + 32) * HSTR;

    // ================= encoder =================
    for (int t = 0; t < T_HIST; ++t) {
        const float* h1c = sm + S_H1 + cur*HBUF;
        const float* h2c = sm + S_H2 + cur*HBUF;
        float* h1n = sm + S_H1 + (cur^1)*HBUF;
        float* h2n = sm + S_H2 + (cur^1)*HBUF;

        float xa0 = sm[S_X + bs*22 + 2*t],        xa1 = sm[S_X + bs*22 + 2*t + 1];
        float xb0 = sm[S_X + (bs+32)*22 + 2*t],   xb1 = sm[S_X + (bs+32)*22 + 2*t + 1];

        u64 ca[4], cb[4];
        init_l0(ca, sm, j0, xa0, xa1);
        init_l0(cb, sm, j0, xb0, xb1);
        gemv1_r2(ca, cb, h1c + rowA, h1c + rowB, sm + S_WT0 + j0);
        float r1a[8], r1b[8];
        tanh8(ca, r1a); tanh8(cb, r1b);
        *reinterpret_cast<float4*>(h1n + rowA + j0)     = make_float4(r1a[0], r1a[1], r1a[2], r1a[3]);
        *reinterpret_cast<float4*>(h1n + rowA + j0 + 4) = make_float4(r1a[4], r1a[5], r1a[6], r1a[7]);
        *reinterpret_cast<float4*>(h1n + rowB + j0)     = make_float4(r1b[0], r1b[1], r1b[2], r1b[3]);
        *reinterpret_cast<float4*>(h1n + rowB + j0 + 4) = make_float4(r1b[4], r1b[5], r1b[6], r1b[7]);
        __syncthreads();

        u64 da[4], db[4];
        init_b1(da, sm, j0);
        init_b1(db, sm, j0);
        gemv2_r2(da, db, h1n + rowA, h1n + rowB, sm + S_WT1 + j0,
                         h2c + rowA, h2c + rowB, sm + S_WT2 + j0);
        float r2a[8], r2b[8];
        tanh8(da, r2a); tanh8(db, r2b);
        *reinterpret_cast<float4*>(h2n + rowA + j0)     = make_float4(r2a[0], r2a[1], r2a[2], r2a[3]);
        *reinterpret_cast<float4*>(h2n + rowA + j0 + 4) = make_float4(r2a[4], r2a[5], r2a[6], r2a[7]);
        *reinterpret_cast<float4*>(h2n + rowB + j0)     = make_float4(r2b[0], r2b[1], r2b[2], r2b[3]);
        *reinterpret_cast<float4*>(h2n + rowB + j0 + 4) = make_float4(r2b[4], r2b[5], r2b[6], r2b[7]);
        __syncthreads();
        cur ^= 1;
    }

    // ================= decoder weight swap =================
    load_phase(sm, dWih0, dWhh0, dbih0, dbhh0, dWih1, dWhh1, dbih1, dbhh1, tid);
    __syncthreads();

    // decoder input feedback kept in registers
    float pa0 = sm[S_X + bs*22 + 2*(T_HIST-1)],      pa1 = sm[S_X + bs*22 + 2*(T_HIST-1) + 1];
    float pb0 = sm[S_X + (bs+32)*22 + 2*(T_HIST-1)], pb1 = sm[S_X + (bs+32)*22 + 2*(T_HIST-1) + 1];
    const float fcb0 = sm[S_FCB], fcb1 = sm[S_FCB + 1];

    // ================= decoder =================
    for (int t = 0; t < T_PRED; ++t) {
        const float* h1c = sm + S_H1 + cur*HBUF;
        const float* h2c = sm + S_H2 + cur*HBUF;
        float* h1n = sm + S_H1 + (cur^1)*HBUF;
        float* h2n = sm + S_H2 + (cur^1)*HBUF;

        u64 ca[4], cb[4];
        init_l0(ca, sm, j0, pa0, pa1);
        init_l0(cb, sm, j0, pb0, pb1);
        gemv1_r2(ca, cb, h1c + rowA, h1c + rowB, sm + S_WT0 + j0);
        float r1a[8], r1b[8];
        tanh8(ca, r1a); tanh8(cb, r1b);
        *reinterpret_cast<float4*>(h1n + rowA + j0)     = make_float4(r1a[0], r1a[1], r1a[2], r1a[3]);
        *reinterpret_cast<float4*>(h1n + rowA + j0 + 4) = make_float4(r1a[4], r1a[5], r1a[6], r1a[7]);
        *reinterpret_cast<float4*>(h1n + rowB + j0)     = make_float4(r1b[0], r1b[1], r1b[2], r1b[3]);
        *reinterpret_cast<float4*>(h1n + rowB + j0 + 4) = make_float4(r1b[4], r1b[5], r1b[6], r1b[7]);
        __syncthreads();

        u64 da[4], db[4];
        init_b1(da, sm, j0);
        init_b1(db, sm, j0);
        gemv2_r2(da, db, h1n + rowA, h1n + rowB, sm + S_WT1 + j0,
                         h2c + rowA, h2c + rowB, sm + S_WT2 + j0);
        float r2a[8], r2b[8];
        tanh8(da, r2a); tanh8(db, r2b);

        // fc partials + h2 writeback
        float qa0 = 0.f, qa1 = 0.f, qb0 = 0.f, qb1 = 0.f;
#pragma unroll
        for (int i = 0; i < 8; ++i) {
            float w0 = sm[S_FCW0 + j0 + i];
            float w1 = sm[S_FCW1 + j0 + i];
            qa0 += r2a[i] * w0;  qa1 += r2a[i] * w1;
            qb0 += r2b[i] * w0;  qb1 += r2b[i] * w1;
        }
        *reinterpret_cast<float4*>(h2n + rowA + j0)     = make_float4(r2a[0], r2a[1], r2a[2], r2a[3]);
        *reinterpret_cast<float4*>(h2n + rowA + j0 + 4) = make_float4(r2a[4], r2a[5], r2a[6], r2a[7]);
        *reinterpret_cast<float4*>(h2n + rowB + j0)     = make_float4(r2b[0], r2b[1], r2b[2], r2b[3]);
        *reinterpret_cast<float4*>(h2n + rowB + j0 + 4) = make_float4(r2b[4], r2b[5], r2b[6], r2b[7]);
        *reinterpret_cast<float2*>(sm + S_PART + jg*128 + bs*2)        = make_float2(qa0, qa1);
        *reinterpret_cast<float2*>(sm + S_PART + jg*128 + (bs+32)*2)   = make_float2(qb0, qb1);
        __syncthreads();

        // every thread reduces fc partials for its own two rows (stays in regs)
        pa0 = fcb0; pa1 = fcb1; pb0 = fcb0; pb1 = fcb1;
#pragma unroll
        for (int g = 0; g < 8; ++g) {
            float2 va = *reinterpret_cast<const float2*>(sm + S_PART + g*128 + bs*2);
            float2 vb = *reinterpret_cast<const float2*>(sm + S_PART + g*128 + (bs+32)*2);
            pa0 += va.x; pa1 += va.y;
            pb0 += vb.x; pb1 += vb.y;
        }
        if (jg == 0) {
            float* opa = out + (size_t)(bg0 + bs)      * (T_PRED*2) + t*2;
            float* opb = out + (size_t)(bg0 + bs + 32) * (T_PRED*2) + t*2;
            opa[0] = pa0; opa[1] = pa1;
            opb[0] = pb0; opb[1] = pb1;
        }
        cur ^= 1;
    }
}

extern "C" void kernel_launch(void* const* d_in, const int* in_sizes, int n_in,
                              void* d_out, int out_size) {
    (void)in_sizes; (void)n_in; (void)out_size;
    const size_t smem = S_TOTAL * sizeof(float);
    cudaFuncSetAttribute(rnn_seq2seq_kernel,
                         cudaFuncAttributeMaxDynamicSharedMemorySize, (int)smem);
    rnn_seq2seq_kernel<<<BATCH / BT, NTHR, smem>>>(
        (const float*)d_in[0],
        (const float*)d_in[1],  (const float*)d_in[2],  (const float*)d_in[3],  (const float*)d_in[4],
        (const float*)d_in[5],  (const float*)d_in[6],  (const float*)d_in[7],  (const float*)d_in[8],
        (const float*)d_in[9],  (const float*)d_in[10], (const float*)d_in[11], (const float*)d_in[12],
        (const float*)d_in[13], (const float*)d_in[14], (const float*)d_in[15], (const float*)d_in[16],
        (const float*)d_in[17], (const float*)d_in[18],
        (float*)d_out);
}

// round 3
// speedup vs baseline: 1.4527x; 1.0006x over previous
#include <cuda_runtime.h>

typedef unsigned long long u64;

static constexpr int NTHR   = 256;   // 32 b-slots x 8 output-groups
static constexpr int BT     = 64;    // batch rows per block (2 per thread)
static constexpr int T_HIST = 11;
static constexpr int T_PRED = 80;
static constexpr int BATCH  = 8192;

// ---- shared memory layout (float offsets) ----
static constexpr int HSTR   = 68;       // h row stride (conflict-free LDS.128)
static constexpr int HBUF   = 64 * HSTR;        // 4352 floats per buffer
static constexpr int S_H1   = 0;                // 2 buffers
static constexpr int S_H2   = 2 * HBUF;         // 8704
static constexpr int S_WT0  = 4 * HBUF;         // 17408: Whh0^T [k][j]
static constexpr int S_WT1  = S_WT0 + 4096;     // Wih1^T
static constexpr int S_WT2  = S_WT1 + 4096;     // Whh1^T
static constexpr int S_WX0  = S_WT2 + 4096;     // Wih0[:,0]
static constexpr int S_WX1  = S_WX0 + 64;
static constexpr int S_B0   = S_WX1 + 64;       // bih0+bhh0
static constexpr int S_B1   = S_B0 + 64;        // bih1+bhh1
static constexpr int S_FCW0 = S_B1 + 64;
static constexpr int S_FCW1 = S_FCW0 + 64;
static constexpr int S_FCB  = S_FCW1 + 64;      // 4 (2 used)
static constexpr int S_X    = S_FCB + 4;        // 64 x 22
static constexpr int S_PART = S_X + 64 * 22;    // 8 x 64 x 2
static constexpr int S_TOTAL= S_PART + 8 * 64 * 2;   // 32516 floats = 130,064 B

// ---- packed f32x2 helpers ----
__device__ __forceinline__ u64 dup2(float x) {
    u64 r; asm("mov.b64 %0, {%1, %1};" : "=l"(r) : "f"(x)); return r;
}
__device__ __forceinline__ u64 fma2(u64 a, u64 b, u64 c) {
    u64 d; asm("fma.rn.f32x2 %0, %1, %2, %3;" : "=l"(d) : "l"(a), "l"(b), "l"(c)); return d;
}
__device__ __forceinline__ void unpk(u64 v, float& lo, float& hi) {
    asm("mov.b64 {%0, %1}, %2;" : "=f"(lo), "=f"(hi) : "l"(v));
}

__device__ __forceinline__ float tanh_fast(float x) {
    float t = __expf(2.0f * x);
    return 1.0f - __fdividef(2.0f, t + 1.0f);
}
__device__ __forceinline__ void tanh8(const u64 c[4], float r[8]) {
#pragma unroll
    for (int i = 0; i < 4; ++i) {
        float lo, hi; unpk(c[i], lo, hi);
        r[2*i]   = tanh_fast(lo);
        r[2*i+1] = tanh_fast(hi);
    }
}

// acc(2 rows) += h_row @ WT   (WT pre-offset by j0, [k][j] layout; h via float4)
__device__ __forceinline__ void gemv1_r2(u64 ca[4], u64 cb[4],
    const float* __restrict__ ha, const float* __restrict__ hb,
    const float* __restrict__ wt) {
#pragma unroll 4
    for (int q = 0; q < 16; ++q) {
        float4 va = *reinterpret_cast<const float4*>(ha + 4*q);
        float4 vb = *reinterpret_cast<const float4*>(hb + 4*q);
        const float* wr = wt + 4*q*64;
        const float fa[4] = {va.x, va.y, va.z, va.w};
        const float fb[4] = {vb.x, vb.y, vb.z, vb.w};
#pragma unroll
        for (int kk = 0; kk < 4; ++kk) {
            ulonglong2 w0 = *reinterpret_cast<const ulonglong2*>(wr + kk*64);
            ulonglong2 w1 = *reinterpret_cast<const ulonglong2*>(wr + kk*64 + 4);
            u64 aa = dup2(fa[kk]);
            u64 bb = dup2(fb[kk]);
            ca[0] = fma2(aa, w0.x, ca[0]); ca[1] = fma2(aa, w0.y, ca[1]);
            ca[2] = fma2(aa, w1.x, ca[2]); ca[3] = fma2(aa, w1.y, ca[3]);
            cb[0] = fma2(bb, w0.x, cb[0]); cb[1] = fma2(bb, w0.y, cb[1]);
            cb[2] = fma2(bb, w1.x, cb[2]); cb[3] = fma2(bb, w1.y, cb[3]);
        }
    }
}

// acc(2 rows) += h1 @ W1 + h2 @ W2   (fused k-loop, layer 1)
__device__ __forceinline__ void gemv2_r2(u64 ca[4], u64 cb[4],
    const float* __restrict__ h1a, const float* __restrict__ h1b,
    const float* __restrict__ w1,
    const float* __restrict__ h2a, const float* __restrict__ h2b,
    const float* __restrict__ w2) {
#pragma unroll 2
    for (int q = 0; q < 16; ++q) {
        float4 v1a = *reinterpret_cast<const float4*>(h1a + 4*q);
        float4 v1b = *reinterpret_cast<const float4*>(h1b + 4*q);
        float4 v2a = *reinterpret_cast<const float4*>(h2a + 4*q);
        float4 v2b = *reinterpret_cast<const float4*>(h2b + 4*q);
        const float* wr1 = w1 + 4*q*64;
        const float* wr2 = w2 + 4*q*64;
        const float f1a[4] = {v1a.x, v1a.y, v1a.z, v1a.w};
        const float f1b[4] = {v1b.x, v1b.y, v1b.z, v1b.w};
        const float f2a[4] = {v2a.x, v2a.y, v2a.z, v2a.w};
        const float f2b[4] = {v2b.x, v2b.y, v2b.z, v2b.w};
#pragma unroll
        for (int kk = 0; kk < 4; ++kk) {
            ulonglong2 u0 = *reinterpret_cast<const ulonglong2*>(wr1 + kk*64);
            ulonglong2 u1 = *reinterpret_cast<const ulonglong2*>(wr1 + kk*64 + 4);
            ulonglong2 v0 = *reinterpret_cast<const ulonglong2*>(wr2 + kk*64);
            ulonglong2 v1 = *reinterpret_cast<const ulonglong2*>(wr2 + kk*64 + 4);
            u64 a1 = dup2(f1a[kk]);
            u64 b1 = dup2(f1b[kk]);
            u64 a2 = dup2(f2a[kk]);
            u64 b2 = dup2(f2b[kk]);
            ca[0] = fma2(a1, u0.x, ca[0]); ca[1] = fma2(a1, u0.y, ca[1]);
            ca[2] = fma2(a1, u1.x, ca[2]); ca[3] = fma2(a1, u1.y, ca[3]);
            cb[0] = fma2(b1, u0.x, cb[0]); cb[1] = fma2(b1, u0.y, cb[1]);
            cb[2] = fma2(b1, u1.x, cb[2]); cb[3] = fma2(b1, u1.y, cb[3]);
            ca[0] = fma2(a2, v0.x, ca[0]); ca[1] = fma2(a2, v0.y, ca[1]);
            ca[2] = fma2(a2, v1.x, ca[2]); ca[3] = fma2(a2, v1.y, ca[3]);
            cb[0] = fma2(b2, v0.x, cb[0]); cb[1] = fma2(b2, v0.y, cb[1]);
            cb[2] = fma2(b2, v1.x, cb[2]); cb[3] = fma2(b2, v1.y, cb[3]);
        }
    }
}

// c = B0 + x0*WX0 + x1*WX1 over j-slice
__device__ __forceinline__ void init_l0(u64 c[4], const float* __restrict__ sm,
                                        int j0, float x0, float x1) {
    const ulonglong2* bp = reinterpret_cast<const ulonglong2*>(sm + S_B0 + j0);
    ulonglong2 b01 = bp[0], b23 = bp[1];
    c[0] = b01.x; c[1] = b01.y; c[2] = b23.x; c[3] = b23.y;
    u64 xa = dup2(x0), xb = dup2(x1);
    const ulonglong2* wa = reinterpret_cast<const ulonglong2*>(sm + S_WX0 + j0);
    const ulonglong2* wb = reinterpret_cast<const ulonglong2*>(sm + S_WX1 + j0);
    ulonglong2 wa0 = wa[0], wa1 = wa[1], wb0 = wb[0], wb1 = wb[1];
    c[0] = fma2(xa, wa0.x, c[0]); c[1] = fma2(xa, wa0.y, c[1]);
    c[2] = fma2(xa, wa1.x, c[2]); c[3] = fma2(xa, wa1.y, c[3]);
    c[0] = fma2(xb, wb0.x, c[0]); c[1] = fma2(xb, wb0.y, c[1]);
    c[2] = fma2(xb, wb1.x, c[2]); c[3] = fma2(xb, wb1.y, c[3]);
}
__device__ __forceinline__ void init_b1(u64 c[4], const float* __restrict__ sm, int j0) {
    const ulonglong2* bp = reinterpret_cast<const ulonglong2*>(sm + S_B1 + j0);
    ulonglong2 a = bp[0], b = bp[1];
    c[0] = a.x; c[1] = a.y; c[2] = b.x; c[3] = b.y;
}

__device__ __forceinline__ void load_phase(float* sm,
    const float* __restrict__ Wih0, const float* __restrict__ Whh0,
    const float* __restrict__ bih0, const float* __restrict__ bhh0,
    const float* __restrict__ Wih1, const float* __restrict__ Whh1,
    const float* __restrict__ bih1, const float* __restrict__ bhh1, int tid) {
    for (int idx = tid; idx < 4096; idx += NTHR) {
        int j = idx & 63, k = idx >> 6;   // dst idx = k*64 + j (conflict-free STS)
        sm[S_WT0 + idx] = Whh0[j*64 + k];
        sm[S_WT1 + idx] = Wih1[j*64 + k];
        sm[S_WT2 + idx] = Whh1[j*64 + k];
    }
    if (tid < 64) {
        sm[S_WX0 + tid] = Wih0[tid*2];
        sm[S_WX1 + tid] = Wih0[tid*2 + 1];
        sm[S_B0 + tid]  = bih0[tid] + bhh0[tid];
        sm[S_B1 + tid]  = bih1[tid] + bhh1[tid];
    }
}

__global__ __launch_bounds__(NTHR, 1)
void rnn_seq2seq_kernel(const float* __restrict__ x,
    const float* __restrict__ eWih0, const float* __restrict__ eWhh0,
    const float* __restrict__ ebih0, const float* __restrict__ ebhh0,
    const float* __restrict__ eWih1, const float* __restrict__ eWhh1,
    const float* __restrict__ ebih1, const float* __restrict__ ebhh1,
    const float* __restrict__ dWih0, const float* __restrict__ dWhh0,
    const float* __restrict__ dbih0, const float* __restrict__ dbhh0,
    const float* __restrict__ dWih1, const float* __restrict__ dWhh1,
    const float* __restrict__ dbih1, const float* __restrict__ dbhh1,
    const float* __restrict__ fcW, const float* __restrict__ fcb,
    float* __restrict__ out)
{
    extern __shared__ float sm[];
    const int tid = threadIdx.x;
    const int bs  = tid & 31;      // batch slot (rows bs and bs+32)
    const int jg  = tid >> 5;      // output group 0..7
    const int j0  = jg * 8;
    const int bg0 = blockIdx.x * BT;

    // zero buffer 0 of both layers
    for (int i = tid; i < HBUF; i += NTHR) {
        sm[S_H1 + i] = 0.f;
        sm[S_H2 + i] = 0.f;
    }
    // stage x tile (64 x 22)
    for (int i = tid; i < BT * 2 * T_HIST; i += NTHR)
        sm[S_X + i] = x[(size_t)bg0 * (2*T_HIST) + i];
    if (tid < 64) { sm[S_FCW0 + tid] = fcW[tid]; sm[S_FCW1 + tid] = fcW[64 + tid]; }
    if (tid < 2)  { sm[S_FCB + tid] = fcb[tid]; }
    load_phase(sm, eWih0, eWhh0, ebih0, ebhh0, eWih1, eWhh1, ebih1, ebhh1, tid);
    __syncthreads();

    int cur = 0;
    const int rowA = bs * HSTR;
    const int rowB = (bs + 32) * HSTR;

    // ================= encoder =================
    for (int t = 0; t < T_HIST; ++t) {
        const float* h1c = sm + S_H1 + cur*HBUF;
        const float* h2c = sm + S_H2 + cur*HBUF;
        float* h1n = sm + S_H1 + (cur^1)*HBUF;
        float* h2n = sm + S_H2 + (cur^1)*HBUF;

        float xa0 = sm[S_X + bs*22 + 2*t],        xa1 = sm[S_X + bs*22 + 2*t + 1];
        float xb0 = sm[S_X + (bs+32)*22 + 2*t],   xb1 = sm[S_X + (bs+32)*22 + 2*t + 1];

        u64 ca[4], cb[4];
        init_l0(ca, sm, j0, xa0, xa1);
        init_l0(cb, sm, j0, xb0, xb1);
        gemv1_r2(ca, cb, h1c + rowA, h1c + rowB, sm + S_WT0 + j0);
        float r1a[8], r1b[8];
        tanh8(ca, r1a); tanh8(cb, r1b);
        *reinterpret_cast<float4*>(h1n + rowA + j0)     = make_float4(r1a[0], r1a[1], r1a[2], r1a[3]);
        *reinterpret_cast<float4*>(h1n + rowA + j0 + 4) = make_float4(r1a[4], r1a[5], r1a[6], r1a[7]);
        *reinterpret_cast<float4*>(h1n + rowB + j0)     = make_float4(r1b[0], r1b[1], r1b[2], r1b[3]);
        *reinterpret_cast<float4*>(h1n + rowB + j0 + 4) = make_float4(r1b[4], r1b[5], r1b[6], r1b[7]);
        __syncthreads();

        u64 da[4], db[4];
        init_b1(da, sm, j0);
        init_b1(db, sm, j0);
        gemv2_r2(da, db, h1n + rowA, h1n + rowB, sm + S_WT1 + j0,
                         h2c + rowA, h2c + rowB, sm + S_WT2 + j0);
        float r2a[8], r2b[8];
        tanh8(da, r2a); tanh8(db, r2b);
        *reinterpret_cast<float4*>(h2n + rowA + j0)     = make_float4(r2a[0], r2a[1], r2a[2], r2a[3]);
        *reinterpret_cast<float4*>(h2n + rowA + j0 + 4) = make_float4(r2a[4], r2a[5], r2a[6], r2a[7]);
        *reinterpret_cast<float4*>(h2n + rowB + j0)     = make_float4(r2b[0], r2b[1], r2b[2], r2b[3]);
        *reinterpret_cast<float4*>(h2n + rowB + j0 + 4) = make_float4(r2b[4], r2b[5], r2b[6], r2b[7]);
        __syncthreads();
        cur ^= 1;
    }

    // ================= decoder weight swap =================
    load_phase(sm, dWih0, dWhh0, dbih0, dbhh0, dWih1, dWhh1, dbih1, dbhh1, tid);
    __syncthreads();

    // decoder input feedback kept in registers
    float pa0 = sm[S_X + bs*22 + 2*(T_HIST-1)],      pa1 = sm[S_X + bs*22 + 2*(T_HIST-1) + 1];
    float pb0 = sm[S_X + (bs+32)*22 + 2*(T_HIST-1)], pb1 = sm[S_X + (bs+32)*22 + 2*(T_HIST-1) + 1];
    const float fcb0 = sm[S_FCB], fcb1 = sm[S_FCB + 1];

    // ================= decoder =================
    for (int t = 0; t < T_PRED; ++t) {
        const float* h1c = sm + S_H1 + cur*HBUF;
        const float* h2c = sm + S_H2 + cur*HBUF;
        float* h1n = sm + S_H1 + (cur^1)*HBUF;
        float* h2n = sm + S_H2 + (cur^1)*HBUF;

        u64 ca[4], cb[4];
        init_l0(ca, sm, j0, pa0, pa1);
        init_l0(cb, sm, j0, pb0, pb1);
        gemv1_r2(ca, cb, h1c + rowA, h1c + rowB, sm + S_WT0 + j0);
        float r1a[8], r1b[8];
        tanh8(ca, r1a); tanh8(cb, r1b);
        *reinterpret_cast<float4*>(h1n + rowA + j0)     = make_float4(r1a[0], r1a[1], r1a[2], r1a[3]);
        *reinterpret_cast<float4*>(h1n + rowA + j0 + 4) = make_float4(r1a[4], r1a[5], r1a[6], r1a[7]);
        *reinterpret_cast<float4*>(h1n + rowB + j0)     = make_float4(r1b[0], r1b[1], r1b[2], r1b[3]);
        *reinterpret_cast<float4*>(h1n + rowB + j0 + 4) = make_float4(r1b[4], r1b[5], r1b[6], r1b[7]);
        __syncthreads();

        u64 da[4], db[4];
        init_b1(da, sm, j0);
        init_b1(db, sm, j0);
        gemv2_r2(da, db, h1n + rowA, h1n + rowB, sm + S_WT1 + j0,
                         h2c + rowA, h2c + rowB, sm + S_WT2 + j0);
        float r2a[8], r2b[8];
        tanh8(da, r2a); tanh8(db, r2b);

        // fc partials + h2 writeback
        float qa0 = 0.f, qa1 = 0.f, qb0 = 0.f, qb1 = 0.f;
#pragma unroll
        for (int i = 0; i < 8; ++i) {
            float w0 = sm[S_FCW0 + j0 + i];
            float w1 = sm[S_FCW1 + j0 + i];
            qa0 += r2a[i] * w0;  qa1 += r2a[i] * w1;
            qb0 += r2b[i] * w0;  qb1 += r2b[i] * w1;
        }
        *reinterpret_cast<float4*>(h2n + rowA + j0)     = make_float4(r2a[0], r2a[1], r2a[2], r2a[3]);
        *reinterpret_cast<float4*>(h2n + rowA + j0 + 4) = make_float4(r2a[4], r2a[5], r2a[6], r2a[7]);
        *reinterpret_cast<float4*>(h2n + rowB + j0)     = make_float4(r2b[0], r2b[1], r2b[2], r2b[3]);
        *reinterpret_cast<float4*>(h2n + rowB + j0 + 4) = make_float4(r2b[4], r2b[5], r2b[6], r2b[7]);
        *reinterpret_cast<float2*>(sm + S_PART + jg*128 + bs*2)        = make_float2(qa0, qa1);
        *reinterpret_cast<float2*>(sm + S_PART + jg*128 + (bs+32)*2)   = make_float2(qb0, qb1);
        __syncthreads();

        // every thread reduces fc partials for its own two rows (stays in regs)
        pa0 = fcb0; pa1 = fcb1; pb0 = fcb0; pb1 = fcb1;
#pragma unroll
        for (int g = 0; g < 8; ++g) {
            float2 va = *reinterpret_cast<const float2*>(sm + S_PART + g*128 + bs*2);
            float2 vb = *reinterpret_cast<const float2*>(sm + S_PART + g*128 + (bs+32)*2);
            pa0 += va.x; pa1 += va.y;
            pb0 += vb.x; pb1 += vb.y;
        }
        if (jg == 0) {
            float* opa = out + (size_t)(bg0 + bs)      * (T_PRED*2) + t*2;
            float* opb = out + (size_t)(bg0 + bs + 32) * (T_PRED*2) + t*2;
            opa[0] = pa0; opa[1] = pa1;
            opb[0] = pb0; opb[1] = pb1;
        }
        cur ^= 1;
    }
}

extern "C" void kernel_launch(void* const* d_in, const int* in_sizes, int n_in,
                              void* d_out, int out_size) {
    (void)in_sizes; (void)n_in; (void)out_size;
    const size_t smem = S_TOTAL * sizeof(float);
    cudaFuncSetAttribute(rnn_seq2seq_kernel,
                         cudaFuncAttributeMaxDynamicSharedMemorySize, (int)smem);
    rnn_seq2seq_kernel<<<BATCH / BT, NTHR, smem>>>(
        (const float*)d_in[0],
        (const float*)d_in[1],  (const float*)d_in[2],  (const float*)d_in[3],  (const float*)d_in[4],
        (const float*)d_in[5],  (const float*)d_in[6],  (const float*)d_in[7],  (const float*)d_in[8],
        (const float*)d_in[9],  (const float*)d_in[10], (const float*)d_in[11], (const float*)d_in[12],
        (const float*)d_in[13], (const float*)d_in[14], (const float*)d_in[15], (const float*)d_in[16],
        (const float*)d_in[17], (const float*)d_in[18],
        (float*)d_out);
}

// round 4
// speedup vs baseline: 1.4662x; 1.0093x over previous
#include <cuda_runtime.h>

typedef unsigned long long u64;

static constexpr int NTHR   = 512;   // 16 warps = 8 jg x 2 bsg; lanes = 16 bl x 2 kh
static constexpr int BT     = 64;
static constexpr int T_HIST = 11;
static constexpr int T_PRED = 80;
static constexpr int BATCH  = 8192;

// ---- shared memory layout (float offsets) ----
static constexpr int HSTR   = 68;
static constexpr int HBUF   = 64 * HSTR;        // 4352
static constexpr int S_H1   = 0;                // 2 buffers
static constexpr int S_H2   = 2 * HBUF;         // 8704
static constexpr int WREG   = 4112;             // staggered weight region (4100 used)
static constexpr int S_WT0  = 4 * HBUF;         // 17408
static constexpr int S_WT1  = S_WT0 + WREG;     // 21520
static constexpr int S_WT2  = S_WT1 + WREG;     // 25632
static constexpr int S_WX0  = S_WT2 + WREG;     // 29744
static constexpr int S_WX1  = S_WX0 + 64;
static constexpr int S_B0   = S_WX1 + 64;
static constexpr int S_B1   = S_B0 + 64;
static constexpr int S_FCW0 = S_B1 + 64;
static constexpr int S_FCW1 = S_FCW0 + 64;
static constexpr int S_FCB  = S_FCW1 + 64;      // 4
static constexpr int S_X    = S_FCB + 4;        // 64 x 22
static constexpr int PSTR   = 20;
static constexpr int S_PART = S_X + 64 * 22;    // 64 x 20
static constexpr int S_TOTAL= S_PART + 64 * PSTR;  // 32820 floats = 131280 B
static constexpr int KSTAG  = 32 * 64 + 4;      // 2052: kh=1 weight base offset

// ---- packed f32x2 helpers ----
__device__ __forceinline__ u64 dup2(float x) {
    u64 r; asm("mov.b64 %0, {%1, %1};" : "=l"(r) : "f"(x)); return r;
}
__device__ __forceinline__ u64 fma2(u64 a, u64 b, u64 c) {
    u64 d; asm("fma.rn.f32x2 %0, %1, %2, %3;" : "=l"(d) : "l"(a), "l"(b), "l"(c)); return d;
}
__device__ __forceinline__ u64 add2(u64 a, u64 b) {
    u64 d; asm("add.rn.f32x2 %0, %1, %2;" : "=l"(d) : "l"(a), "l"(b)); return d;
}
__device__ __forceinline__ void unpk(u64 v, float& lo, float& hi) {
    asm("mov.b64 {%0, %1}, %2;" : "=f"(lo), "=f"(hi) : "l"(v));
}
__device__ __forceinline__ float tanh_fast(float x) {
    float t = __expf(2.0f * x);
    return 1.0f - __fdividef(2.0f, t + 1.0f);
}

// cross-k-half combine: lane keeps its own row's full sum (kh0 -> rowA, kh1 -> rowB)
__device__ __forceinline__ void combine8(const u64 ca[4], const u64 cb[4],
                                         int kh, u64 s[4]) {
#pragma unroll
    for (int i = 0; i < 4; ++i) {
        u64 send = kh ? ca[i] : cb[i];
        u64 keep = kh ? cb[i] : ca[i];
        u64 recv = __shfl_xor_sync(0xffffffffu, send, 16);
        s[i] = add2(keep, recv);
    }
}
__device__ __forceinline__ void tanh8(const u64 s[4], float r[8]) {
#pragma unroll
    for (int i = 0; i < 4; ++i) {
        float lo, hi; unpk(s[i], lo, hi);
        r[2*i]   = tanh_fast(lo);
        r[2*i+1] = tanh_fast(hi);
    }
}

// acc(2 rows) += h[k-half] @ W-slice   (32 k iterations; pointers pre-offset)
__device__ __forceinline__ void gemv1(u64 ca[4], u64 cb[4],
    const float* __restrict__ ha, const float* __restrict__ hb,
    const float* __restrict__ wt) {
#pragma unroll
    for (int q = 0; q < 8; ++q) {
        float4 va = *reinterpret_cast<const float4*>(ha + 4*q);
        float4 vb = *reinterpret_cast<const float4*>(hb + 4*q);
        const float* wr = wt + 4*q*64;
        const float fa[4] = {va.x, va.y, va.z, va.w};
        const float fb[4] = {vb.x, vb.y, vb.z, vb.w};
#pragma unroll
        for (int kk = 0; kk < 4; ++kk) {
            ulonglong2 w0 = *reinterpret_cast<const ulonglong2*>(wr + kk*64);
            ulonglong2 w1 = *reinterpret_cast<const ulonglong2*>(wr + kk*64 + 4);
            u64 aa = dup2(fa[kk]), bb = dup2(fb[kk]);
            ca[0] = fma2(aa, w0.x, ca[0]); ca[1] = fma2(aa, w0.y, ca[1]);
            ca[2] = fma2(aa, w1.x, ca[2]); ca[3] = fma2(aa, w1.y, ca[3]);
            cb[0] = fma2(bb, w0.x, cb[0]); cb[1] = fma2(bb, w0.y, cb[1]);
            cb[2] = fma2(bb, w1.x, cb[2]); cb[3] = fma2(bb, w1.y, cb[3]);
        }
    }
}

// acc(2 rows) += h1[k-half] @ W1 + h2[k-half] @ W2
__device__ __forceinline__ void gemv2(u64 ca[4], u64 cb[4],
    const float* __restrict__ h1a, const float* __restrict__ h1b,
    const float* __restrict__ w1,
    const float* __restrict__ h2a, const float* __restrict__ h2b,
    const float* __restrict__ w2) {
#pragma unroll
    for (int q = 0; q < 8; ++q) {
        float4 v1a = *reinterpret_cast<const float4*>(h1a + 4*q);
        float4 v1b = *reinterpret_cast<const float4*>(h1b + 4*q);
        float4 v2a = *reinterpret_cast<const float4*>(h2a + 4*q);
        float4 v2b = *reinterpret_cast<const float4*>(h2b + 4*q);
        const float* wr1 = w1 + 4*q*64;
        const float* wr2 = w2 + 4*q*64;
        const float f1a[4] = {v1a.x, v1a.y, v1a.z, v1a.w};
        const float f1b[4] = {v1b.x, v1b.y, v1b.z, v1b.w};
        const float f2a[4] = {v2a.x, v2a.y, v2a.z, v2a.w};
        const float f2b[4] = {v2b.x, v2b.y, v2b.z, v2b.w};
#pragma unroll
        for (int kk = 0; kk < 4; ++kk) {
            ulonglong2 u0 = *reinterpret_cast<const ulonglong2*>(wr1 + kk*64);
            ulonglong2 u1 = *reinterpret_cast<const ulonglong2*>(wr1 + kk*64 + 4);
            ulonglong2 v0 = *reinterpret_cast<const ulonglong2*>(wr2 + kk*64);
            ulonglong2 v1 = *reinterpret_cast<const ulonglong2*>(wr2 + kk*64 + 4);
            u64 a1 = dup2(f1a[kk]), b1 = dup2(f1b[kk]);
            u64 a2 = dup2(f2a[kk]), b2 = dup2(f2b[kk]);
            ca[0] = fma2(a1, u0.x, ca[0]); ca[1] = fma2(a1, u0.y, ca[1]);
            ca[2] = fma2(a1, u1.x, ca[2]); ca[3] = fma2(a1, u1.y, ca[3]);
            cb[0] = fma2(b1, u0.x, cb[0]); cb[1] = fma2(b1, u0.y, cb[1]);
            cb[2] = fma2(b1, u1.x, cb[2]); cb[3] = fma2(b1, u1.y, cb[3]);
            ca[0] = fma2(a2, v0.x, ca[0]); ca[1] = fma2(a2, v0.y, ca[1]);
            ca[2] = fma2(a2, v1.x, ca[2]); ca[3] = fma2(a2, v1.y, ca[3]);
            cb[0] = fma2(b2, v0.x, cb[0]); cb[1] = fma2(b2, v0.y, cb[1]);
            cb[2] = fma2(b2, v1.x, cb[2]); cb[3] = fma2(b2, v1.y, cb[3]);
        }
    }
}

// layer-0 init (kh==0 lanes): c = B0 + x0*WX0 + x1*WX1 for both rows
__device__ __forceinline__ void init_l0(u64 ca[4], u64 cb[4],
    const float* __restrict__ sm, int j0,
    float xa0, float xa1, float xb0, float xb1) {
    const ulonglong2* bp  = reinterpret_cast<const ulonglong2*>(sm + S_B0 + j0);
    const ulonglong2* wap = reinterpret_cast<const ulonglong2*>(sm + S_WX0 + j0);
    const ulonglong2* wbp = reinterpret_cast<const ulonglong2*>(sm + S_WX1 + j0);
    ulonglong2 b01 = bp[0],  b23 = bp[1];
    ulonglong2 wa0 = wap[0], wa1 = wap[1];
    ulonglong2 wb0 = wbp[0], wb1 = wbp[1];
    u64 bq[4] = {b01.x, b01.y, b23.x, b23.y};
    u64 w0q[4] = {wa0.x, wa0.y, wa1.x, wa1.y};
    u64 w1q[4] = {wb0.x, wb0.y, wb1.x, wb1.y};
    u64 da0 = dup2(xa0), da1 = dup2(xa1), db0 = dup2(xb0), db1 = dup2(xb1);
#pragma unroll
    for (int i = 0; i < 4; ++i) {
        ca[i] = fma2(da1, w1q[i], fma2(da0, w0q[i], bq[i]));
        cb[i] = fma2(db1, w1q[i], fma2(db0, w0q[i], bq[i]));
    }
}

__device__ __forceinline__ void load_phase(float* sm,
    const float* __restrict__ Wih0, const float* __restrict__ Whh0,
    const float* __restrict__ bih0, const float* __restrict__ bhh0,
    const float* __restrict__ Wih1, const float* __restrict__ Whh1,
    const float* __restrict__ bih1, const float* __restrict__ bhh1, int tid) {
    for (int idx = tid; idx < 4096; idx += NTHR) {
        int j = idx & 63, k = idx >> 6;
        int dst = k*64 + j + ((k >> 5) << 2);   // +4 stagger for k>=32
        sm[S_WT0 + dst] = Whh0[j*64 + k];
        sm[S_WT1 + dst] = Wih1[j*64 + k];
        sm[S_WT2 + dst] = Whh1[j*64 + k];
    }
    if (tid < 64) {
        sm[S_WX0 + tid] = Wih0[tid*2];
        sm[S_WX1 + tid] = Wih0[tid*2 + 1];
        sm[S_B0 + tid]  = bih0[tid] + bhh0[tid];
        sm[S_B1 + tid]  = bih1[tid] + bhh1[tid];
    }
}

__global__ __launch_bounds__(NTHR, 1)
void rnn_seq2seq_kernel(const float* __restrict__ x,
    const float* __restrict__ eWih0, const float* __restrict__ eWhh0,
    const float* __restrict__ ebih0, const float* __restrict__ ebhh0,
    const float* __restrict__ eWih1, const float* __restrict__ eWhh1,
    const float* __restrict__ ebih1, const float* __restrict__ ebhh1,
    const float* __restrict__ dWih0, const float* __restrict__ dWhh0,
    const float* __restrict__ dbih0, const float* __restrict__ dbhh0,
    const float* __restrict__ dWih1, const float* __restrict__ dWhh1,
    const float* __restrict__ dbih1, const float* __restrict__ dbhh1,
    const float* __restrict__ fcW, const float* __restrict__ fcb,
    float* __restrict__ out)
{
    extern __shared__ float sm[];
    const int tid  = threadIdx.x;
    const int w    = tid >> 5;
    const int lane = tid & 31;
    const int jg   = w & 7;
    const int bsg  = w >> 3;
    const int j0   = jg * 8;
    const int bl   = lane & 15;
    const int kh   = lane >> 4;
    const int rA   = bsg * 32 + bl;     // partial rows handled by this thread
    const int rB   = rA + 16;
    const int rS   = kh ? rB : rA;      // row this lane owns post-combine
    const int kb   = kh * 32;
    const int wofs = kh * KSTAG;
    const int bg0  = blockIdx.x * BT;

    // zero h buffer 0 of both layers
    for (int i = tid; i < HBUF; i += NTHR) { sm[S_H1 + i] = 0.f; sm[S_H2 + i] = 0.f; }
    for (int i = tid; i < BT * 2 * T_HIST; i += NTHR)
        sm[S_X + i] = x[(size_t)bg0 * (2*T_HIST) + i];
    if (tid < 64) { sm[S_FCW0 + tid] = fcW[tid]; sm[S_FCW1 + tid] = fcW[64 + tid]; }
    if (tid < 2)  { sm[S_FCB + tid] = fcb[tid]; }
    load_phase(sm, eWih0, eWhh0, ebih0, ebhh0, eWih1, eWhh1, ebih1, ebhh1, tid);
    __syncthreads();

    int cur = 0;
    const int offA = rA * HSTR + kb;
    const int offB = rB * HSTR + kb;
    const int stO  = rS * HSTR + j0;    // h store offset for owned row

    // ================= encoder: 1 sync per step =================
    for (int t = 0; t < T_HIST; ++t) {
        const float* h1c = sm + S_H1 + cur*HBUF;
        const float* h2c = sm + S_H2 + cur*HBUF;
        float* h1n = sm + S_H1 + (cur^1)*HBUF;
        float* h2n = sm + S_H2 + (cur^1)*HBUF;

        u64 ca[4] = {0,0,0,0}, cb[4] = {0,0,0,0};
        if (kh == 0) {
            float xa0 = sm[S_X + rA*22 + 2*t], xa1 = sm[S_X + rA*22 + 2*t + 1];
            float xb0 = sm[S_X + rB*22 + 2*t], xb1 = sm[S_X + rB*22 + 2*t + 1];
            init_l0(ca, cb, sm, j0, xa0, xa1, xb0, xb1);
        }
        gemv1(ca, cb, h1c + offA, h1c + offB, sm + S_WT0 + j0 + wofs);
        u64 s[4]; combine8(ca, cb, kh, s);
        float r1[8]; tanh8(s, r1);
        *reinterpret_cast<float4*>(h1n + stO)     = make_float4(r1[0], r1[1], r1[2], r1[3]);
        *reinterpret_cast<float4*>(h1n + stO + 4) = make_float4(r1[4], r1[5], r1[6], r1[7]);
        __syncthreads();

        u64 da[4] = {0,0,0,0}, db[4] = {0,0,0,0};
        if (kh == 0) {
            const ulonglong2* bp = reinterpret_cast<const ulonglong2*>(sm + S_B1 + j0);
            ulonglong2 b01 = bp[0], b23 = bp[1];
            da[0] = b01.x; da[1] = b01.y; da[2] = b23.x; da[3] = b23.y;
            db[0] = b01.x; db[1] = b01.y; db[2] = b23.x; db[3] = b23.y;
        }
        gemv2(da, db, h1n + offA, h1n + offB, sm + S_WT1 + j0 + wofs,
                      h2c + offA, h2c + offB, sm + S_WT2 + j0 + wofs);
        u64 s2[4]; combine8(da, db, kh, s2);
        float r2[8]; tanh8(s2, r2);
        *reinterpret_cast<float4*>(h2n + stO)     = make_float4(r2[0], r2[1], r2[2], r2[3]);
        *reinterpret_cast<float4*>(h2n + stO + 4) = make_float4(r2[4], r2[5], r2[6], r2[7]);
        cur ^= 1;
        // second barrier not needed: next step's sync orders all remaining hazards
    }

    // ================= decoder weight swap =================
    __syncthreads();   // encoder gemv reads must finish before weights change
    load_phase(sm, dWih0, dWhh0, dbih0, dbhh0, dWih1, dWhh1, dbih1, dbhh1, tid);
    __syncthreads();

    // decoder feedback: preds for rows rA, rB kept in registers
    float pa0 = sm[S_X + rA*22 + 2*(T_HIST-1)], pa1 = sm[S_X + rA*22 + 2*(T_HIST-1) + 1];
    float pb0 = sm[S_X + rB*22 + 2*(T_HIST-1)], pb1 = sm[S_X + rB*22 + 2*(T_HIST-1) + 1];
    const float fcb0 = sm[S_FCB], fcb1 = sm[S_FCB + 1];

    // ================= decoder: 2 syncs per step =================
    for (int t = 0; t < T_PRED; ++t) {
        const float* h1c = sm + S_H1 + cur*HBUF;
        const float* h2c = sm + S_H2 + cur*HBUF;
        float* h1n = sm + S_H1 + (cur^1)*HBUF;
        float* h2n = sm + S_H2 + (cur^1)*HBUF;

        u64 ca[4] = {0,0,0,0}, cb[4] = {0,0,0,0};
        if (kh == 0)
            init_l0(ca, cb, sm, j0, pa0, pa1, pb0, pb1);
        gemv1(ca, cb, h1c + offA, h1c + offB, sm + S_WT0 + j0 + wofs);
        u64 s[4]; combine8(ca, cb, kh, s);
        float r1[8]; tanh8(s, r1);
        *reinterpret_cast<float4*>(h1n + stO)     = make_float4(r1[0], r1[1], r1[2], r1[3]);
        *reinterpret_cast<float4*>(h1n + stO + 4) = make_float4(r1[4], r1[5], r1[6], r1[7]);
        __syncthreads();

        u64 da[4] = {0,0,0,0}, db[4] = {0,0,0,0};
        if (kh == 0) {
            const ulonglong2* bp = reinterpret_cast<const ulonglong2*>(sm + S_B1 + j0);
            ulonglong2 b01 = bp[0], b23 = bp[1];
            da[0] = b01.x; da[1] = b01.y; da[2] = b23.x; da[3] = b23.y;
            db[0] = b01.x; db[1] = b01.y; db[2] = b23.x; db[3] = b23.y;
        }
        gemv2(da, db, h1n + offA, h1n + offB, sm + S_WT1 + j0 + wofs,
                      h2c + offA, h2c + offB, sm + S_WT2 + j0 + wofs);
        u64 s2[4]; combine8(da, db, kh, s2);
        float r2[8]; tanh8(s2, r2);

        // fc partials for the owned row
        float4 f0a = *reinterpret_cast<const float4*>(sm + S_FCW0 + j0);
        float4 f0b = *reinterpret_cast<const float4*>(sm + S_FCW0 + j0 + 4);
        float4 f1a = *reinterpret_cast<const float4*>(sm + S_FCW1 + j0);
        float4 f1b = *reinterpret_cast<const float4*>(sm + S_FCW1 + j0 + 4);
        float q0 = r2[0]*f0a.x + r2[1]*f0a.y + r2[2]*f0a.z + r2[3]*f0a.w
                 + r2[4]*f0b.x + r2[5]*f0b.y + r2[6]*f0b.z + r2[7]*f0b.w;
        float q1 = r2[0]*f1a.x + r2[1]*f1a.y + r2[2]*f1a.z + r2[3]*f1a.w
                 + r2[4]*f1b.x + r2[5]*f1b.y + r2[6]*f1b.z + r2[7]*f1b.w;

        *reinterpret_cast<float4*>(h2n + stO)     = make_float4(r2[0], r2[1], r2[2], r2[3]);
        *reinterpret_cast<float4*>(h2n + stO + 4) = make_float4(r2[4], r2[5], r2[6], r2[7]);
        *reinterpret_cast<float2*>(sm + S_PART + rS*PSTR + jg*2) = make_float2(q0, q1);
        __syncthreads();

        // reduce fc partials for owned row, then exchange across kh halves
        float pS0 = fcb0, pS1 = fcb1;
#pragma unroll
        for (int g = 0; g < 8; ++g) {
            float2 v = *reinterpret_cast<const float2*>(sm + S_PART + rS*PSTR + g*2);
            pS0 += v.x; pS1 += v.y;
        }
        float o0 = __shfl_xor_sync(0xffffffffu, pS0, 16);
        float o1 = __shfl_xor_sync(0xffffffffu, pS1, 16);
        pa0 = kh ? o0 : pS0;  pa1 = kh ? o1 : pS1;   // rowA pred
        pb0 = kh ? pS0 : o0;  pb1 = kh ? pS1 : o1;   // rowB pred

        if (jg == 0) {   // warps 0 and 8: 64 distinct rS rows
            float* op = out + (size_t)(bg0 + rS) * (T_PRED*2) + t*2;
            op[0] = pS0; op[1] = pS1;
        }
        cur ^= 1;
    }
}

extern "C" void kernel_launch(void* const* d_in, const int* in_sizes, int n_in,
                              void* d_out, int out_size) {
    (void)in_sizes; (void)n_in; (void)out_size;
    const size_t smem = S_TOTAL * sizeof(float);
    cudaFuncSetAttribute(rnn_seq2seq_kernel,
                         cudaFuncAttributeMaxDynamicSharedMemorySize, (int)smem);
    rnn_seq2seq_kernel<<<BATCH / BT, NTHR, smem>>>(
        (const float*)d_in[0],
        (const float*)d_in[1],  (const float*)d_in[2],  (const float*)d_in[3],  (const float*)d_in[4],
        (const float*)d_in[5],  (const float*)d_in[6],  (const float*)d_in[7],  (const float*)d_in[8],
        (const float*)d_in[9],  (const float*)d_in[10], (const float*)d_in[11], (const float*)d_in[12],
        (const float*)d_in[13], (const float*)d_in[14], (const float*)d_in[15], (const float*)d_in[16],
        (const float*)d_in[17], (const float*)d_in[18],
        (float*)d_out);
}

// round 5
// speedup vs baseline: 1.6288x; 1.1109x over previous
#include <cuda_runtime.h>

typedef unsigned long long u64;

static constexpr int NTHR   = 256;   // 8 warps = 8 j-groups; lanes = 16 bl x 2 kh
static constexpr int BT     = 64;
static constexpr int T_HIST = 11;
static constexpr int T_PRED = 80;
static constexpr int BATCH  = 8192;

// ---- shared memory layout (float offsets) ----
static constexpr int HSTR   = 68;
static constexpr int HBUF   = 64 * HSTR;        // 4352
static constexpr int S_H1   = 0;                // 2 buffers
static constexpr int S_H2   = 2 * HBUF;         // 8704
static constexpr int WREG   = 4112;
static constexpr int S_WT0  = 4 * HBUF;         // 17408
static constexpr int S_WT1  = S_WT0 + WREG;
static constexpr int S_WT2  = S_WT1 + WREG;
static constexpr int S_WX0  = S_WT2 + WREG;
static constexpr int S_WX1  = S_WX0 + 64;
static constexpr int S_B0   = S_WX1 + 64;
static constexpr int S_B1   = S_B0 + 64;
static constexpr int S_FCW0 = S_B1 + 64;
static constexpr int S_FCW1 = S_FCW0 + 64;
static constexpr int S_FCB  = S_FCW1 + 64;      // 4
static constexpr int S_X    = S_FCB + 4;        // 64 x 22
static constexpr int PSTR   = 20;
static constexpr int S_PART = S_X + 64 * 22;
static constexpr int S_TOTAL= S_PART + 64 * PSTR;   // ~131 KB
static constexpr int KSTAG  = 32 * 64 + 4;      // kh=1 weight base offset

// ---- packed f32x2 helpers ----
__device__ __forceinline__ u64 dup2(float x) {
    u64 r; asm("mov.b64 %0, {%1, %1};" : "=l"(r) : "f"(x)); return r;
}
__device__ __forceinline__ u64 fma2(u64 a, u64 b, u64 c) {
    u64 d; asm("fma.rn.f32x2 %0, %1, %2, %3;" : "=l"(d) : "l"(a), "l"(b), "l"(c)); return d;
}
__device__ __forceinline__ u64 add2(u64 a, u64 b) {
    u64 d; asm("add.rn.f32x2 %0, %1, %2;" : "=l"(d) : "l"(a), "l"(b)); return d;
}
__device__ __forceinline__ void unpk(u64 v, float& lo, float& hi) {
    asm("mov.b64 {%0, %1}, %2;" : "=f"(lo), "=f"(hi) : "l"(v));
}
__device__ __forceinline__ float tanh_fast(float x) {
    float t = __expf(2.0f * x);
    return 1.0f - __fdividef(2.0f, t + 1.0f);
}

// exchange partial sums across kh halves; lane ends with FULL sums of its
// 2 owned rows: kh0 owns r0,r1 (slots 0,1), kh1 owns r2,r3 (slots 2,3).
__device__ __forceinline__ void exchange4(const u64 a[4][4], int kh, u64 own[2][4]) {
#pragma unroll
    for (int i = 0; i < 2; ++i) {
#pragma unroll
        for (int c = 0; c < 4; ++c) {
            u64 keep = kh ? a[2 + i][c] : a[i][c];
            u64 send = kh ? a[i][c]     : a[2 + i][c];
            u64 recv = __shfl_xor_sync(0xffffffffu, send, 16);
            own[i][c] = add2(keep, recv);
        }
    }
}
__device__ __forceinline__ void tanh8(const u64 s[4], float r[8]) {
#pragma unroll
    for (int i = 0; i < 4; ++i) {
        float lo, hi; unpk(s[i], lo, hi);
        r[2*i]   = tanh_fast(lo);
        r[2*i+1] = tanh_fast(hi);
    }
}

// acc(4 rows) += h[k-half] @ W-slice
__device__ __forceinline__ void gemv1_4(u64 a[4][4],
    const float* __restrict__ h, const int off[4],
    const float* __restrict__ wt) {
#pragma unroll 2
    for (int q = 0; q < 8; ++q) {
        float fa[4][4];
#pragma unroll
        for (int r = 0; r < 4; ++r) {
            float4 v = *reinterpret_cast<const float4*>(h + off[r] + 4*q);
            fa[r][0] = v.x; fa[r][1] = v.y; fa[r][2] = v.z; fa[r][3] = v.w;
        }
        const float* wr = wt + 4*q*64;
#pragma unroll
        for (int kk = 0; kk < 4; ++kk) {
            ulonglong2 w0 = *reinterpret_cast<const ulonglong2*>(wr + kk*64);
            ulonglong2 w1 = *reinterpret_cast<const ulonglong2*>(wr + kk*64 + 4);
#pragma unroll
            for (int r = 0; r < 4; ++r) {
                u64 d = dup2(fa[r][kk]);
                a[r][0] = fma2(d, w0.x, a[r][0]);
                a[r][1] = fma2(d, w0.y, a[r][1]);
                a[r][2] = fma2(d, w1.x, a[r][2]);
                a[r][3] = fma2(d, w1.y, a[r][3]);
            }
        }
    }
}

// acc(4 rows) += h1[k-half] @ W1 + h2[k-half] @ W2
__device__ __forceinline__ void gemv2_4(u64 a[4][4],
    const float* __restrict__ h1, const float* __restrict__ h2, const int off[4],
    const float* __restrict__ w1, const float* __restrict__ w2) {
#pragma unroll 2
    for (int q = 0; q < 8; ++q) {
        float f1[4][4], f2[4][4];
#pragma unroll
        for (int r = 0; r < 4; ++r) {
            float4 v1 = *reinterpret_cast<const float4*>(h1 + off[r] + 4*q);
            float4 v2 = *reinterpret_cast<const float4*>(h2 + off[r] + 4*q);
            f1[r][0] = v1.x; f1[r][1] = v1.y; f1[r][2] = v1.z; f1[r][3] = v1.w;
            f2[r][0] = v2.x; f2[r][1] = v2.y; f2[r][2] = v2.z; f2[r][3] = v2.w;
        }
        const float* wr1 = w1 + 4*q*64;
        const float* wr2 = w2 + 4*q*64;
#pragma unroll
        for (int kk = 0; kk < 4; ++kk) {
            ulonglong2 u0 = *reinterpret_cast<const ulonglong2*>(wr1 + kk*64);
            ulonglong2 u1 = *reinterpret_cast<const ulonglong2*>(wr1 + kk*64 + 4);
            ulonglong2 v0 = *reinterpret_cast<const ulonglong2*>(wr2 + kk*64);
            ulonglong2 v1 = *reinterpret_cast<const ulonglong2*>(wr2 + kk*64 + 4);
#pragma unroll
            for (int r = 0; r < 4; ++r) {
                u64 d1 = dup2(f1[r][kk]);
                u64 d2 = dup2(f2[r][kk]);
                a[r][0] = fma2(d1, u0.x, a[r][0]);
                a[r][1] = fma2(d1, u0.y, a[r][1]);
                a[r][2] = fma2(d1, u1.x, a[r][2]);
                a[r][3] = fma2(d1, u1.y, a[r][3]);
                a[r][0] = fma2(d2, v0.x, a[r][0]);
                a[r][1] = fma2(d2, v0.y, a[r][1]);
                a[r][2] = fma2(d2, v1.x, a[r][2]);
                a[r][3] = fma2(d2, v1.y, a[r][3]);
            }
        }
    }
}

// layer-0 init (kh==0 lanes): a[r] = B0 + x0*WX0 + x1*WX1
__device__ __forceinline__ void init_l0_4(u64 a[4][4], const float* __restrict__ sm,
                                          int j0, const float px[4][2]) {
    const ulonglong2* bp  = reinterpret_cast<const ulonglong2*>(sm + S_B0 + j0);
    const ulonglong2* wap = reinterpret_cast<const ulonglong2*>(sm + S_WX0 + j0);
    const ulonglong2* wbp = reinterpret_cast<const ulonglong2*>(sm + S_WX1 + j0);
    ulonglong2 b01 = bp[0],  b23 = bp[1];
    ulonglong2 wa0 = wap[0], wa1 = wap[1];
    ulonglong2 wb0 = wbp[0], wb1 = wbp[1];
    u64 bq[4]  = {b01.x, b01.y, b23.x, b23.y};
    u64 w0q[4] = {wa0.x, wa0.y, wa1.x, wa1.y};
    u64 w1q[4] = {wb0.x, wb0.y, wb1.x, wb1.y};
#pragma unroll
    for (int r = 0; r < 4; ++r) {
        u64 d0 = dup2(px[r][0]), d1 = dup2(px[r][1]);
#pragma unroll
        for (int c = 0; c < 4; ++c)
            a[r][c] = fma2(d1, w1q[c], fma2(d0, w0q[c], bq[c]));
    }
}
__device__ __forceinline__ void init_b1_4(u64 a[4][4], const float* __restrict__ sm, int j0) {
    const ulonglong2* bp = reinterpret_cast<const ulonglong2*>(sm + S_B1 + j0);
    ulonglong2 b01 = bp[0], b23 = bp[1];
#pragma unroll
    for (int r = 0; r < 4; ++r) {
        a[r][0] = b01.x; a[r][1] = b01.y; a[r][2] = b23.x; a[r][3] = b23.y;
    }
}

__device__ __forceinline__ void load_phase(float* sm,
    const float* __restrict__ Wih0, const float* __restrict__ Whh0,
    const float* __restrict__ bih0, const float* __restrict__ bhh0,
    const float* __restrict__ Wih1, const float* __restrict__ Whh1,
    const float* __restrict__ bih1, const float* __restrict__ bhh1, int tid) {
    for (int idx = tid; idx < 4096; idx += NTHR) {
        int j = idx & 63, k = idx >> 6;
        int dst = k*64 + j + ((k >> 5) << 2);   // +4 stagger for k>=32
        sm[S_WT0 + dst] = Whh0[j*64 + k];
        sm[S_WT1 + dst] = Wih1[j*64 + k];
        sm[S_WT2 + dst] = Whh1[j*64 + k];
    }
    if (tid < 64) {
        sm[S_WX0 + tid] = Wih0[tid*2];
        sm[S_WX1 + tid] = Wih0[tid*2 + 1];
        sm[S_B0 + tid]  = bih0[tid] + bhh0[tid];
        sm[S_B1 + tid]  = bih1[tid] + bhh1[tid];
    }
}

__global__ __launch_bounds__(NTHR, 1)
void rnn_seq2seq_kernel(const float* __restrict__ x,
    const float* __restrict__ eWih0, const float* __restrict__ eWhh0,
    const float* __restrict__ ebih0, const float* __restrict__ ebhh0,
    const float* __restrict__ eWih1, const float* __restrict__ eWhh1,
    const float* __restrict__ ebih1, const float* __restrict__ ebhh1,
    const float* __restrict__ dWih0, const float* __restrict__ dWhh0,
    const float* __restrict__ dbih0, const float* __restrict__ dbhh0,
    const float* __restrict__ dWih1, const float* __restrict__ dWhh1,
    const float* __restrict__ dbih1, const float* __restrict__ dbhh1,
    const float* __restrict__ fcW, const float* __restrict__ fcb,
    float* __restrict__ out)
{
    extern __shared__ float sm[];
    const int tid  = threadIdx.x;
    const int jg   = tid >> 5;          // 8 warps = 8 j-groups
    const int lane = tid & 31;
    const int j0   = jg * 8;
    const int bl   = lane & 15;
    const int kh   = lane >> 4;
    const int kb   = kh * 32;
    const int wofs = kh * KSTAG;
    const int bg0  = blockIdx.x * BT;

    // rows handled (partials): r = bl + 16*i, i=0..3. owned rows (full sums):
    // kh0 -> bl, bl+16 ; kh1 -> bl+32, bl+48
    int off[4], rowOwn[2];
#pragma unroll
    for (int r = 0; r < 4; ++r) off[r] = (bl + 16*r) * HSTR + kb;
#pragma unroll
    for (int i = 0; i < 2; ++i) rowOwn[i] = bl + 16 * (2*kh + i);
    const int stO0 = rowOwn[0] * HSTR + j0;
    const int stO1 = rowOwn[1] * HSTR + j0;

    // init smem
    for (int i = tid; i < HBUF; i += NTHR) { sm[S_H1 + i] = 0.f; sm[S_H2 + i] = 0.f; }
    for (int i = tid; i < BT * 2 * T_HIST; i += NTHR)
        sm[S_X + i] = x[(size_t)bg0 * (2*T_HIST) + i];
    if (tid < 64) { sm[S_FCW0 + tid] = fcW[tid]; sm[S_FCW1 + tid] = fcW[64 + tid]; }
    if (tid < 2)  { sm[S_FCB + tid] = fcb[tid]; }
    load_phase(sm, eWih0, eWhh0, ebih0, ebhh0, eWih1, eWhh1, ebih1, ebhh1, tid);
    __syncthreads();

    int cur = 0;

    // ================= encoder: 1 sync per step =================
    for (int t = 0; t < T_HIST; ++t) {
        const float* h1c = sm + S_H1 + cur*HBUF;
        const float* h2c = sm + S_H2 + cur*HBUF;
        float* h1n = sm + S_H1 + (cur^1)*HBUF;
        float* h2n = sm + S_H2 + (cur^1)*HBUF;

        u64 a[4][4];
        if (kh == 0) {
            float px[4][2];
#pragma unroll
            for (int r = 0; r < 4; ++r) {
                int row = bl + 16*r;
                px[r][0] = sm[S_X + row*22 + 2*t];
                px[r][1] = sm[S_X + row*22 + 2*t + 1];
            }
            init_l0_4(a, sm, j0, px);
        } else {
#pragma unroll
            for (int r = 0; r < 4; ++r) { a[r][0]=0; a[r][1]=0; a[r][2]=0; a[r][3]=0; }
        }
        gemv1_4(a, h1c, off, sm + S_WT0 + j0 + wofs);
        u64 own[2][4];
        exchange4(a, kh, own);
        float r1a[8], r1b[8];
        tanh8(own[0], r1a); tanh8(own[1], r1b);
        *reinterpret_cast<float4*>(h1n + stO0)     = make_float4(r1a[0], r1a[1], r1a[2], r1a[3]);
        *reinterpret_cast<float4*>(h1n + stO0 + 4) = make_float4(r1a[4], r1a[5], r1a[6], r1a[7]);
        *reinterpret_cast<float4*>(h1n + stO1)     = make_float4(r1b[0], r1b[1], r1b[2], r1b[3]);
        *reinterpret_cast<float4*>(h1n + stO1 + 4) = make_float4(r1b[4], r1b[5], r1b[6], r1b[7]);
        __syncthreads();

        u64 d[4][4];
        if (kh == 0) init_b1_4(d, sm, j0);
        else {
#pragma unroll
            for (int r = 0; r < 4; ++r) { d[r][0]=0; d[r][1]=0; d[r][2]=0; d[r][3]=0; }
        }
        gemv2_4(d, h1n, h2c, off, sm + S_WT1 + j0 + wofs, sm + S_WT2 + j0 + wofs);
        u64 own2[2][4];
        exchange4(d, kh, own2);
        float r2a[8], r2b[8];
        tanh8(own2[0], r2a); tanh8(own2[1], r2b);
        *reinterpret_cast<float4*>(h2n + stO0)     = make_float4(r2a[0], r2a[1], r2a[2], r2a[3]);
        *reinterpret_cast<float4*>(h2n + stO0 + 4) = make_float4(r2a[4], r2a[5], r2a[6], r2a[7]);
        *reinterpret_cast<float4*>(h2n + stO1)     = make_float4(r2b[0], r2b[1], r2b[2], r2b[3]);
        *reinterpret_cast<float4*>(h2n + stO1 + 4) = make_float4(r2b[4], r2b[5], r2b[6], r2b[7]);
        cur ^= 1;
    }

    // ================= decoder weight swap =================
    __syncthreads();
    load_phase(sm, dWih0, dWhh0, dbih0, dbhh0, dWih1, dWhh1, dbih1, dbhh1, tid);
    __syncthreads();

    // feedback inputs for all 4 partial rows, kept in registers
    float px[4][2];
#pragma unroll
    for (int r = 0; r < 4; ++r) {
        int row = bl + 16*r;
        px[r][0] = sm[S_X + row*22 + 2*(T_HIST-1)];
        px[r][1] = sm[S_X + row*22 + 2*(T_HIST-1) + 1];
    }
    const float fcb0 = sm[S_FCB], fcb1 = sm[S_FCB + 1];
    float4 f0a = *reinterpret_cast<const float4*>(sm + S_FCW0 + j0);
    float4 f0b = *reinterpret_cast<const float4*>(sm + S_FCW0 + j0 + 4);
    float4 f1a = *reinterpret_cast<const float4*>(sm + S_FCW1 + j0);
    float4 f1b = *reinterpret_cast<const float4*>(sm + S_FCW1 + j0 + 4);

    // ================= decoder: 2 syncs per step =================
    for (int t = 0; t < T_PRED; ++t) {
        const float* h1c = sm + S_H1 + cur*HBUF;
        const float* h2c = sm + S_H2 + cur*HBUF;
        float* h1n = sm + S_H1 + (cur^1)*HBUF;
        float* h2n = sm + S_H2 + (cur^1)*HBUF;

        u64 a[4][4];
        if (kh == 0) init_l0_4(a, sm, j0, px);
        else {
#pragma unroll
            for (int r = 0; r < 4; ++r) { a[r][0]=0; a[r][1]=0; a[r][2]=0; a[r][3]=0; }
        }
        gemv1_4(a, h1c, off, sm + S_WT0 + j0 + wofs);
        u64 own[2][4];
        exchange4(a, kh, own);
        float r1a[8], r1b[8];
        tanh8(own[0], r1a); tanh8(own[1], r1b);
        *reinterpret_cast<float4*>(h1n + stO0)     = make_float4(r1a[0], r1a[1], r1a[2], r1a[3]);
        *reinterpret_cast<float4*>(h1n + stO0 + 4) = make_float4(r1a[4], r1a[5], r1a[6], r1a[7]);
        *reinterpret_cast<float4*>(h1n + stO1)     = make_float4(r1b[0], r1b[1], r1b[2], r1b[3]);
        *reinterpret_cast<float4*>(h1n + stO1 + 4) = make_float4(r1b[4], r1b[5], r1b[6], r1b[7]);
        __syncthreads();

        u64 d[4][4];
        if (kh == 0) init_b1_4(d, sm, j0);
        else {
#pragma unroll
            for (int r = 0; r < 4; ++r) { d[r][0]=0; d[r][1]=0; d[r][2]=0; d[r][3]=0; }
        }
        gemv2_4(d, h1n, h2c, off, sm + S_WT1 + j0 + wofs, sm + S_WT2 + j0 + wofs);
        u64 own2[2][4];
        exchange4(d, kh, own2);
        float r2a[8], r2b[8];
        tanh8(own2[0], r2a); tanh8(own2[1], r2b);

        // fc partials for owned rows + h2 writeback
        float qa0 = r2a[0]*f0a.x + r2a[1]*f0a.y + r2a[2]*f0a.z + r2a[3]*f0a.w
                  + r2a[4]*f0b.x + r2a[5]*f0b.y + r2a[6]*f0b.z + r2a[7]*f0b.w;
        float qa1 = r2a[0]*f1a.x + r2a[1]*f1a.y + r2a[2]*f1a.z + r2a[3]*f1a.w
                  + r2a[4]*f1b.x + r2a[5]*f1b.y + r2a[6]*f1b.z + r2a[7]*f1b.w;
        float qb0 = r2b[0]*f0a.x + r2b[1]*f0a.y + r2b[2]*f0a.z + r2b[3]*f0a.w
                  + r2b[4]*f0b.x + r2b[5]*f0b.y + r2b[6]*f0b.z + r2b[7]*f0b.w;
        float qb1 = r2b[0]*f1a.x + r2b[1]*f1a.y + r2b[2]*f1a.z + r2b[3]*f1a.w
                  + r2b[4]*f1b.x + r2b[5]*f1b.y + r2b[6]*f1b.z + r2b[7]*f1b.w;

        *reinterpret_cast<float4*>(h2n + stO0)     = make_float4(r2a[0], r2a[1], r2a[2], r2a[3]);
        *reinterpret_cast<float4*>(h2n + stO0 + 4) = make_float4(r2a[4], r2a[5], r2a[6], r2a[7]);
        *reinterpret_cast<float4*>(h2n + stO1)     = make_float4(r2b[0], r2b[1], r2b[2], r2b[3]);
        *reinterpret_cast<float4*>(h2n + stO1 + 4) = make_float4(r2b[4], r2b[5], r2b[6], r2b[7]);
        *reinterpret_cast<float2*>(sm + S_PART + rowOwn[0]*PSTR + jg*2) = make_float2(qa0, qa1);
        *reinterpret_cast<float2*>(sm + S_PART + rowOwn[1]*PSTR + jg*2) = make_float2(qb0, qb1);
        __syncthreads();

        // reduce fc partials for owned rows
        float po[2][2];
#pragma unroll
        for (int i = 0; i < 2; ++i) {
            po[i][0] = fcb0; po[i][1] = fcb1;
#pragma unroll
            for (int g = 0; g < 8; ++g) {
                float2 v = *reinterpret_cast<const float2*>(sm + S_PART + rowOwn[i]*PSTR + g*2);
                po[i][0] += v.x; po[i][1] += v.y;
            }
        }
        // exchange preds across kh so every lane has feedback for all 4 rows
        float rx[2][2];
#pragma unroll
        for (int i = 0; i < 2; ++i) {
            rx[i][0] = __shfl_xor_sync(0xffffffffu, po[i][0], 16);
            rx[i][1] = __shfl_xor_sync(0xffffffffu, po[i][1], 16);
        }
#pragma unroll
        for (int i = 0; i < 2; ++i) {
            px[2*kh + i][0]     = po[i][0];  px[2*kh + i][1]     = po[i][1];
            px[2*(1-kh) + i][0] = rx[i][0];  px[2*(1-kh) + i][1] = rx[i][1];
        }

        if (jg == 0) {  // warp 0 lanes cover all 64 rows (2 owned each)
#pragma unroll
            for (int i = 0; i < 2; ++i) {
                float* op = out + (size_t)(bg0 + rowOwn[i]) * (T_PRED*2) + t*2;
                op[0] = po[i][0]; op[1] = po[i][1];
            }
        }
        cur ^= 1;
    }
}

extern "C" void kernel_launch(void* const* d_in, const int* in_sizes, int n_in,
                              void* d_out, int out_size) {
    (void)in_sizes; (void)n_in; (void)out_size;
    const size_t smem = S_TOTAL * sizeof(float);
    cudaFuncSetAttribute(rnn_seq2seq_kernel,
                         cudaFuncAttributeMaxDynamicSharedMemorySize, (int)smem);
    rnn_seq2seq_kernel<<<BATCH / BT, NTHR, smem>>>(
        (const float*)d_in[0],
        (const float*)d_in[1],  (const float*)d_in[2],  (const float*)d_in[3],  (const float*)d_in[4],
        (const float*)d_in[5],  (const float*)d_in[6],  (const float*)d_in[7],  (const float*)d_in[8],
        (const float*)d_in[9],  (const float*)d_in[10], (const float*)d_in[11], (const float*)d_in[12],
        (const float*)d_in[13], (const float*)d_in[14], (const float*)d_in[15], (const float*)d_in[16],
        (const float*)d_in[17], (const float*)d_in[18],
        (float*)d_out);
}

// round 7
// speedup vs baseline: 2.2672x; 1.3919x over previous
#include <cuda_runtime.h>
#include <cuda_bf16.h>
#include <mma.h>
#include <cstdint>

using namespace nvcuda;

static constexpr int NTHR   = 256;   // 8 warps = 4 n-tiles x 2 m-halves
static constexpr int BT     = 64;
static constexpr int T_HIST = 11;
static constexpr int T_PRED = 80;
static constexpr int BATCH  = 8192;
static constexpr int GRID   = BATCH / BT;   // 128

// ---- shared memory byte offsets ----
static constexpr int HLD    = 72;            // bf16 leading dim (144B rows, 16B aligned)
static constexpr int DLD    = 68;            // fp32 leading dim (272B rows)
static constexpr int O_H1HI = 0;             // 64 x 72 bf16 = 9216 B
static constexpr int O_H1LO = 9216;
static constexpr int O_H2HI = 18432;
static constexpr int O_H2LO = 27648;
static constexpr int O_D    = 36864;         // 64 x 68 fp32 = 17408 B
static constexpr int O_WSTG = 54272;         // weight staging: hi(9216) + lo(9216)
static constexpr int O_X    = 72704;         // 64 x 22 fp32
static constexpr int O_B0   = 78336;
static constexpr int O_B1   = 78592;
static constexpr int O_WX0  = 78848;
static constexpr int O_WX1  = 79104;
static constexpr int O_FCW0 = 79360;
static constexpr int O_FCW1 = 79616;
static constexpr int O_FCB  = 79872;
static constexpr int SMEM_TOTAL = 79904;

typedef wmma::fragment<wmma::matrix_a, 16, 16, 16, __nv_bfloat16, wmma::row_major> AFrag;
typedef wmma::fragment<wmma::matrix_b, 16, 16, 16, __nv_bfloat16, wmma::row_major> BFrag;
typedef wmma::fragment<wmma::accumulator, 16, 16, 16, float> CFrag;

__device__ __forceinline__ float tanh_fast(float x) {
    float t = __expf(2.0f * x);
    return 1.0f - __fdividef(2.0f, t + 1.0f);
}
// two fp32 -> packed hi bf16x2 (truncated) + lo bf16x2 (rounded residual)
__device__ __forceinline__ void split2(float f0, float f1, uint32_t& hi, uint32_t& lo) {
    uint32_t u0 = __float_as_uint(f0) & 0xffff0000u;
    uint32_t u1 = __float_as_uint(f1) & 0xffff0000u;
    float l0 = f0 - __uint_as_float(u0);
    float l1 = f1 - __uint_as_float(u1);
    hi = u1 | (u0 >> 16);
    asm("cvt.rn.bf16x2.f32 %0, %1, %2;" : "=r"(lo) : "f"(l1), "f"(l0));
}

__global__ __launch_bounds__(NTHR, 1)
void rnn_wmma_kernel(const float* __restrict__ x,
    const float* __restrict__ eWih0, const float* __restrict__ eWhh0,
    const float* __restrict__ ebih0, const float* __restrict__ ebhh0,
    const float* __restrict__ eWih1, const float* __restrict__ eWhh1,
    const float* __restrict__ ebih1, const float* __restrict__ ebhh1,
    const float* __restrict__ dWih0, const float* __restrict__ dWhh0,
    const float* __restrict__ dbih0, const float* __restrict__ dbhh0,
    const float* __restrict__ dWih1, const float* __restrict__ dWhh1,
    const float* __restrict__ dbih1, const float* __restrict__ dbhh1,
    const float* __restrict__ fcW, const float* __restrict__ fcb,
    float* __restrict__ out)
{
    extern __shared__ __align__(128) char smb[];
    float* smf = (float*)smb;
    const int tid  = threadIdx.x;
    const int wid  = tid >> 5;
    const int nt   = wid & 3;          // n-tile: cols nt*16 .. nt*16+15
    const int mh   = wid >> 2;         // m-half: m-tiles 2*mh, 2*mh+1
    const int row  = tid >> 2;         // epilogue row (0..63)
    const int cb   = (tid & 3) * 16;   // epilogue column base
    const int bg0  = blockIdx.x * BT;

    __nv_bfloat16* h1hi = (__nv_bfloat16*)(smb + O_H1HI);
    __nv_bfloat16* h1lo = (__nv_bfloat16*)(smb + O_H1LO);
    __nv_bfloat16* h2hi = (__nv_bfloat16*)(smb + O_H2HI);
    __nv_bfloat16* h2lo = (__nv_bfloat16*)(smb + O_H2LO);
    __nv_bfloat16* wstg_hi = (__nv_bfloat16*)(smb + O_WSTG);
    __nv_bfloat16* wstg_lo = wstg_hi + 4608;
    float* D = smf + O_D / 4;

    // persistent weight fragments: [0]=W0hi [1]=W0lo [2]=W1hi [3]=W1lo [4]=W2hi [5]=W2lo
    BFrag bW[6][4];

    // ---------------- one-time init ----------------
    for (int i = tid; i < 9216; i += NTHR)            // zero all 4 h arrays (36864 B)
        ((uint32_t*)(smb + O_H1HI))[i] = 0u;
    for (int i = tid; i < BT * 2 * T_HIST; i += NTHR)
        smf[O_X/4 + i] = x[(size_t)bg0 * (2*T_HIST) + i];
    if (tid < 64) { smf[O_FCW0/4 + tid] = fcW[tid]; smf[O_FCW1/4 + tid] = fcW[64 + tid]; }
    if (tid < 2)  { smf[O_FCB/4 + tid] = fcb[tid]; }

    // ---------------- phase setup (weights -> b_frags, biases -> smem) ----------
    auto setup_phase = [&](const float* W0, const float* W1, const float* W2,
                           const float* Wih0, const float* bih0, const float* bhh0,
                           const float* bih1, const float* bhh1) {
        const float* Ws[3] = {W0, W1, W2};
#pragma unroll 1
        for (int w = 0; w < 3; ++w) {
            __syncthreads();   // staging buffer free (prior frag loads done)
            for (int idx = tid; idx < 4096; idx += NTHR) {
                int k = idx >> 6, j = idx & 63;
                float wv = Ws[w][j*64 + k];           // WT[k][j] = W[j][k]
                uint32_t u = __float_as_uint(wv) & 0xffff0000u;
                unsigned short hb = (unsigned short)(u >> 16);
                __nv_bfloat16 lb = __float2bfloat16(wv - __uint_as_float(u));
                *(unsigned short*)&wstg_hi[k*HLD + j] = hb;
                wstg_lo[k*HLD + j] = lb;
            }
            __syncthreads();
#pragma unroll
            for (int k = 0; k < 4; ++k) {
                wmma::load_matrix_sync(bW[2*w][k],   wstg_hi + k*16*HLD + nt*16, HLD);
                wmma::load_matrix_sync(bW[2*w+1][k], wstg_lo + k*16*HLD + nt*16, HLD);
            }
        }
        if (tid < 64) {
            smf[O_WX0/4 + tid] = Wih0[tid*2];
            smf[O_WX1/4 + tid] = Wih0[tid*2 + 1];
            smf[O_B0/4  + tid] = bih0[tid] + bhh0[tid];
            smf[O_B1/4  + tid] = bih1[tid] + bhh1[tid];
        }
        __syncthreads();
    };

    // ---------------- GEMM phases ----------------
    auto do_l0 = [&]() {   // D = h1(hi,lo) @ W0(hi,lo), 3 terms
#pragma unroll
        for (int mi = 0; mi < 2; ++mi) {
            int mrow = (mh*2 + mi) * 16;
            CFrag acc; wmma::fill_fragment(acc, 0.0f);
#pragma unroll
            for (int k = 0; k < 4; ++k) {
                AFrag ah, al;
                wmma::load_matrix_sync(ah, h1hi + mrow*HLD + k*16, HLD);
                wmma::load_matrix_sync(al, h1lo + mrow*HLD + k*16, HLD);
                wmma::mma_sync(acc, ah, bW[0][k], acc);
                wmma::mma_sync(acc, ah, bW[1][k], acc);
                wmma::mma_sync(acc, al, bW[0][k], acc);
            }
            wmma::store_matrix_sync(D + mrow*DLD + nt*16, acc, DLD, wmma::mem_row_major);
        }
    };
    auto do_l1 = [&]() {   // D = h1new @ W1 + h2 @ W2, 6 terms
#pragma unroll
        for (int mi = 0; mi < 2; ++mi) {
            int mrow = (mh*2 + mi) * 16;
            CFrag acc; wmma::fill_fragment(acc, 0.0f);
#pragma unroll
            for (int k = 0; k < 4; ++k) {
                AFrag ah, al, bh, blo;
                wmma::load_matrix_sync(ah,  h1hi + mrow*HLD + k*16, HLD);
                wmma::load_matrix_sync(al,  h1lo + mrow*HLD + k*16, HLD);
                wmma::load_matrix_sync(bh,  h2hi + mrow*HLD + k*16, HLD);
                wmma::load_matrix_sync(blo, h2lo + mrow*HLD + k*16, HLD);
                wmma::mma_sync(acc, ah,  bW[2][k], acc);
                wmma::mma_sync(acc, ah,  bW[3][k], acc);
                wmma::mma_sync(acc, al,  bW[2][k], acc);
                wmma::mma_sync(acc, bh,  bW[4][k], acc);
                wmma::mma_sync(acc, bh,  bW[5][k], acc);
                wmma::mma_sync(acc, blo, bW[4][k], acc);
            }
            wmma::store_matrix_sync(D + mrow*DLD + nt*16, acc, DLD, wmma::mem_row_major);
        }
    };

    // ---------------- epilogues ----------------
    // eplg1: v = tanh(D + b0 + x0*wx0 + x1*wx1) -> h1 hi/lo
    auto eplg1 = [&](float x0, float x1) {
        const float* drow = D + row*DLD + cb;
        const float* bp   = smf + O_B0/4  + cb;
        const float* w0p  = smf + O_WX0/4 + cb;
        const float* w1p  = smf + O_WX1/4 + cb;
        uint32_t hi8[8], lo8[8];
#pragma unroll
        for (int p = 0; p < 8; ++p) {
            float v0 = tanh_fast(drow[2*p]   + bp[2*p]   + x0*w0p[2*p]   + x1*w1p[2*p]);
            float v1 = tanh_fast(drow[2*p+1] + bp[2*p+1] + x0*w0p[2*p+1] + x1*w1p[2*p+1]);
            split2(v0, v1, hi8[p], lo8[p]);
        }
        uint4* ph = (uint4*)((char*)h1hi + row*144 + cb*2);
        uint4* pl = (uint4*)((char*)h1lo + row*144 + cb*2);
        ph[0] = make_uint4(hi8[0], hi8[1], hi8[2], hi8[3]);
        ph[1] = make_uint4(hi8[4], hi8[5], hi8[6], hi8[7]);
        pl[0] = make_uint4(lo8[0], lo8[1], lo8[2], lo8[3]);
        pl[1] = make_uint4(lo8[4], lo8[5], lo8[6], lo8[7]);
    };
    // eplg2: v = tanh(D + b1) -> h2 hi/lo; optional fc partials (q0,q1)
    auto eplg2 = [&](bool want_fc, float& q0, float& q1) {
        const float* drow = D + row*DLD + cb;
        const float* bp   = smf + O_B1/4   + cb;
        const float* f0   = smf + O_FCW0/4 + cb;
        const float* f1   = smf + O_FCW1/4 + cb;
        uint32_t hi8[8], lo8[8];
        q0 = 0.f; q1 = 0.f;
#pragma unroll
        for (int p = 0; p < 8; ++p) {
            float v0 = tanh_fast(drow[2*p]   + bp[2*p]);
            float v1 = tanh_fast(drow[2*p+1] + bp[2*p+1]);
            if (want_fc) {
                q0 += v0*f0[2*p] + v1*f0[2*p+1];
                q1 += v0*f1[2*p] + v1*f1[2*p+1];
            }
            split2(v0, v1, hi8[p], lo8[p]);
        }
        uint4* ph = (uint4*)((char*)h2hi + row*144 + cb*2);
        uint4* pl = (uint4*)((char*)h2lo + row*144 + cb*2);
        ph[0] = make_uint4(hi8[0], hi8[1], hi8[2], hi8[3]);
        ph[1] = make_uint4(hi8[4], hi8[5], hi8[6], hi8[7]);
        pl[0] = make_uint4(lo8[0], lo8[1], lo8[2], lo8[3]);
        pl[1] = make_uint4(lo8[4], lo8[5], lo8[6], lo8[7]);
    };

    // ==================== encoder ====================
    setup_phase(eWhh0, eWih1, eWhh1, eWih0, ebih0, ebhh0, ebih1, ebhh1);
    for (int t = 0; t < T_HIST; ++t) {
        do_l0();
        __syncthreads();
        eplg1(smf[O_X/4 + row*22 + 2*t], smf[O_X/4 + row*22 + 2*t + 1]);
        __syncthreads();
        do_l1();
        __syncthreads();
        { float dq0, dq1; eplg2(false, dq0, dq1); }
        __syncthreads();
    }

    // ==================== decoder ====================
    setup_phase(dWhh0, dWih1, dWhh1, dWih0, dbih0, dbhh0, dbih1, dbhh1);
    float px0 = smf[O_X/4 + row*22 + 2*(T_HIST-1)];
    float px1 = smf[O_X/4 + row*22 + 2*(T_HIST-1) + 1];
    const float fcb0 = smf[O_FCB/4], fcb1 = smf[O_FCB/4 + 1];

    for (int t = 0; t < T_PRED; ++t) {
        do_l0();
        __syncthreads();
        eplg1(px0, px1);
        __syncthreads();
        do_l1();
        __syncthreads();
        float q0, q1;
        eplg2(true, q0, q1);
        // reduce fc partials across the 4 lanes of this row (lanes tid&3 = 0..3)
        q0 += __shfl_xor_sync(0xffffffffu, q0, 1);
        q1 += __shfl_xor_sync(0xffffffffu, q1, 1);
        q0 += __shfl_xor_sync(0xffffffffu, q0, 2);
        q1 += __shfl_xor_sync(0xffffffffu, q1, 2);
        px0 = q0 + fcb0;
        px1 = q1 + fcb1;
        if ((tid & 3) == 0) {
            float* op = out + (size_t)(bg0 + row) * (T_PRED*2) + t*2;
            op[0] = px0; op[1] = px1;
        }
        __syncthreads();
    }
}

extern "C" void kernel_launch(void* const* d_in, const int* in_sizes, int n_in,
                              void* d_out, int out_size) {
    (void)in_sizes; (void)n_in; (void)out_size;
    cudaFuncSetAttribute(rnn_wmma_kernel,
                         cudaFuncAttributeMaxDynamicSharedMemorySize, SMEM_TOTAL);
    rnn_wmma_kernel<<<GRID, NTHR, SMEM_TOTAL>>>(
        (const float*)d_in[0],
        (const float*)d_in[1],  (const float*)d_in[2],  (const float*)d_in[3],  (const float*)d_in[4],
        (const float*)d_in[5],  (const float*)d_in[6],  (const float*)d_in[7],  (const float*)d_in[8],
        (const float*)d_in[9],  (const float*)d_in[10], (const float*)d_in[11], (const float*)d_in[12],
        (const float*)d_in[13], (const float*)d_in[14], (const float*)d_in[15], (const float*)d_in[16],
        (const float*)d_in[17], (const float*)d_in[18],
        (float*)d_out);
}

// round 8
// speedup vs baseline: 2.4515x; 1.0813x over previous
#include <cuda_runtime.h>
#include <cuda_bf16.h>
#include <mma.h>
#include <cstdint>

using namespace nvcuda;

static constexpr int NTHR   = 256;   // 8 warps = 4 n-tiles x 2 m-halves
static constexpr int BT     = 64;
static constexpr int T_HIST = 11;
static constexpr int T_PRED = 80;
static constexpr int BATCH  = 8192;
static constexpr int GRID   = BATCH / BT;   // 128

// ---- shared memory byte offsets ----
static constexpr int HLD    = 72;            // bf16 leading dim
static constexpr int DLD    = 68;            // fp32 leading dim
static constexpr int O_H1HI = 0;             // 64 x 72 bf16 = 9216 B
static constexpr int O_H1LO = 9216;
static constexpr int O_H2HI = 18432;
static constexpr int O_H2LO = 27648;
static constexpr int O_D1   = 36864;         // 64 x 68 fp32 = 17408 B
static constexpr int O_D2   = 54272;
static constexpr int O_WSTG = 71680;         // staging hi(9216) + lo(9216)
static constexpr int O_X    = 90112;         // 64 x 22 fp32
static constexpr int O_B0   = 95744;
static constexpr int O_B1   = 96000;
static constexpr int O_WX0  = 96256;
static constexpr int O_WX1  = 96512;
static constexpr int O_FCW0 = 96768;
static constexpr int O_FCW1 = 97024;
static constexpr int O_FCB  = 97280;
static constexpr int SMEM_TOTAL = 97296;

typedef wmma::fragment<wmma::matrix_a, 16, 16, 16, __nv_bfloat16, wmma::row_major> AFrag;
typedef wmma::fragment<wmma::matrix_b, 16, 16, 16, __nv_bfloat16, wmma::row_major> BFrag;
typedef wmma::fragment<wmma::accumulator, 16, 16, 16, float> CFrag;

__device__ __forceinline__ float tanh_fast(float x) {
    float t = __expf(2.0f * x);
    return 1.0f - __fdividef(2.0f, t + 1.0f);
}
__device__ __forceinline__ void split2(float f0, float f1, uint32_t& hi, uint32_t& lo) {
    uint32_t u0 = __float_as_uint(f0) & 0xffff0000u;
    uint32_t u1 = __float_as_uint(f1) & 0xffff0000u;
    float l0 = f0 - __uint_as_float(u0);
    float l1 = f1 - __uint_as_float(u1);
    hi = u1 | (u0 >> 16);
    asm("cvt.rn.bf16x2.f32 %0, %1, %2;" : "=r"(lo) : "f"(l1), "f"(l0));
}

__global__ __launch_bounds__(NTHR, 1)
void rnn_wmma_kernel(const float* __restrict__ x,
    const float* __restrict__ eWih0, const float* __restrict__ eWhh0,
    const float* __restrict__ ebih0, const float* __restrict__ ebhh0,
    const float* __restrict__ eWih1, const float* __restrict__ eWhh1,
    const float* __restrict__ ebih1, const float* __restrict__ ebhh1,
    const float* __restrict__ dWih0, const float* __restrict__ dWhh0,
    const float* __restrict__ dbih0, const float* __restrict__ dbhh0,
    const float* __restrict__ dWih1, const float* __restrict__ dWhh1,
    const float* __restrict__ dbih1, const float* __restrict__ dbhh1,
    const float* __restrict__ fcW, const float* __restrict__ fcb,
    float* __restrict__ out)
{
    extern __shared__ __align__(128) char smb[];
    float* smf = (float*)smb;
    const int tid  = threadIdx.x;
    const int wid  = tid >> 5;
    const int nt   = wid & 3;          // n-tile
    const int mh   = wid >> 2;         // m-half
    const int row  = tid >> 2;         // epilogue row (0..63)
    const int cb   = (tid & 3) * 16;   // epilogue column base
    const int bg0  = blockIdx.x * BT;

    __nv_bfloat16* h1hi = (__nv_bfloat16*)(smb + O_H1HI);
    __nv_bfloat16* h1lo = (__nv_bfloat16*)(smb + O_H1LO);
    __nv_bfloat16* h2hi = (__nv_bfloat16*)(smb + O_H2HI);
    __nv_bfloat16* h2lo = (__nv_bfloat16*)(smb + O_H2LO);
    __nv_bfloat16* wstg_hi = (__nv_bfloat16*)(smb + O_WSTG);
    __nv_bfloat16* wstg_lo = wstg_hi + 4608;
    float* D1 = smf + O_D1 / 4;
    float* D2 = smf + O_D2 / 4;

    // persistent weight frags: [0]=W0hi [1]=W0lo [2]=W1hi [3]=W1lo [4]=W2hi [5]=W2lo
    BFrag bW[6][4];

    // ---------------- one-time init ----------------
    for (int i = tid; i < 9216; i += NTHR)            // zero all 4 h arrays
        ((uint32_t*)(smb + O_H1HI))[i] = 0u;
    for (int i = tid; i < BT * 2 * T_HIST; i += NTHR)
        smf[O_X/4 + i] = x[(size_t)bg0 * (2*T_HIST) + i];
    if (tid < 64) { smf[O_FCW0/4 + tid] = fcW[tid]; smf[O_FCW1/4 + tid] = fcW[64 + tid]; }
    if (tid < 2)  { smf[O_FCB/4 + tid] = fcb[tid]; }

    // ---------------- phase setup ----------------
    auto setup_phase = [&](const float* W0, const float* W1, const float* W2,
                           const float* Wih0, const float* bih0, const float* bhh0,
                           const float* bih1, const float* bhh1) {
        const float* Ws[3] = {W0, W1, W2};
#pragma unroll 1
        for (int w = 0; w < 3; ++w) {
            __syncthreads();
            for (int idx = tid; idx < 4096; idx += NTHR) {
                int k = idx >> 6, j = idx & 63;
                float wv = Ws[w][j*64 + k];           // WT[k][j] = W[j][k]
                uint32_t u = __float_as_uint(wv) & 0xffff0000u;
                unsigned short hb = (unsigned short)(u >> 16);
                __nv_bfloat16 lb = __float2bfloat16(wv - __uint_as_float(u));
                *(unsigned short*)&wstg_hi[k*HLD + j] = hb;
                wstg_lo[k*HLD + j] = lb;
            }
            __syncthreads();
#pragma unroll
            for (int k = 0; k < 4; ++k) {
                wmma::load_matrix_sync(bW[2*w][k],   wstg_hi + k*16*HLD + nt*16, HLD);
                wmma::load_matrix_sync(bW[2*w+1][k], wstg_lo + k*16*HLD + nt*16, HLD);
            }
        }
        if (tid < 64) {
            smf[O_WX0/4 + tid] = Wih0[tid*2];
            smf[O_WX1/4 + tid] = Wih0[tid*2 + 1];
            smf[O_B0/4  + tid] = bih0[tid] + bhh0[tid];
            smf[O_B1/4  + tid] = bih1[tid] + bhh1[tid];
        }
        __syncthreads();
    };

    // ---------------- GEMM phases ----------------
    // l0 alone: D1 = h1 @ W0 (3 terms) — prologue only
    auto mma_l0 = [&]() {
#pragma unroll
        for (int mi = 0; mi < 2; ++mi) {
            int mrow = (mh*2 + mi) * 16;
            CFrag acc; wmma::fill_fragment(acc, 0.0f);
#pragma unroll
            for (int k = 0; k < 4; ++k) {
                AFrag ah, al;
                wmma::load_matrix_sync(ah, h1hi + mrow*HLD + k*16, HLD);
                wmma::load_matrix_sync(al, h1lo + mrow*HLD + k*16, HLD);
                wmma::mma_sync(acc, ah, bW[0][k], acc);
                wmma::mma_sync(acc, ah, bW[1][k], acc);
                wmma::mma_sync(acc, al, bW[0][k], acc);
            }
            wmma::store_matrix_sync(D1 + mrow*DLD + nt*16, acc, DLD, wmma::mem_row_major);
        }
    };
    // fused: D2 = h1@W1 + h2@W2 (6 terms); optionally D1 = h1@W0 (3 terms, next step)
    auto mma_fused = [&](bool with_l0) {
#pragma unroll
        for (int mi = 0; mi < 2; ++mi) {
            int mrow = (mh*2 + mi) * 16;
            CFrag acc2; wmma::fill_fragment(acc2, 0.0f);
            CFrag acc1; wmma::fill_fragment(acc1, 0.0f);
#pragma unroll
            for (int k = 0; k < 4; ++k) {
                AFrag a1h, a1l, a2h, a2l;
                wmma::load_matrix_sync(a1h, h1hi + mrow*HLD + k*16, HLD);
                wmma::load_matrix_sync(a1l, h1lo + mrow*HLD + k*16, HLD);
                wmma::load_matrix_sync(a2h, h2hi + mrow*HLD + k*16, HLD);
                wmma::load_matrix_sync(a2l, h2lo + mrow*HLD + k*16, HLD);
                wmma::mma_sync(acc2, a1h, bW[2][k], acc2);
                wmma::mma_sync(acc2, a1h, bW[3][k], acc2);
                wmma::mma_sync(acc2, a1l, bW[2][k], acc2);
                wmma::mma_sync(acc2, a2h, bW[4][k], acc2);
                wmma::mma_sync(acc2, a2h, bW[5][k], acc2);
                wmma::mma_sync(acc2, a2l, bW[4][k], acc2);
                if (with_l0) {
                    wmma::mma_sync(acc1, a1h, bW[0][k], acc1);
                    wmma::mma_sync(acc1, a1h, bW[1][k], acc1);
                    wmma::mma_sync(acc1, a1l, bW[0][k], acc1);
                }
            }
            wmma::store_matrix_sync(D2 + mrow*DLD + nt*16, acc2, DLD, wmma::mem_row_major);
            if (with_l0)
                wmma::store_matrix_sync(D1 + mrow*DLD + nt*16, acc1, DLD, wmma::mem_row_major);
        }
    };

    // ---------------- epilogues (thread-local, no barrier inside) ----------------
    auto eplg1 = [&](float x0, float x1) {
        const float* drow = D1 + row*DLD + cb;
        const float* bp   = smf + O_B0/4  + cb;
        const float* w0p  = smf + O_WX0/4 + cb;
        const float* w1p  = smf + O_WX1/4 + cb;
        uint32_t hi8[8], lo8[8];
#pragma unroll
        for (int p = 0; p < 8; ++p) {
            float v0 = tanh_fast(drow[2*p]   + bp[2*p]   + x0*w0p[2*p]   + x1*w1p[2*p]);
            float v1 = tanh_fast(drow[2*p+1] + bp[2*p+1] + x0*w0p[2*p+1] + x1*w1p[2*p+1]);
            split2(v0, v1, hi8[p], lo8[p]);
        }
        uint4* ph = (uint4*)((char*)h1hi + row*144 + cb*2);
        uint4* pl = (uint4*)((char*)h1lo + row*144 + cb*2);
        ph[0] = make_uint4(hi8[0], hi8[1], hi8[2], hi8[3]);
        ph[1] = make_uint4(hi8[4], hi8[5], hi8[6], hi8[7]);
        pl[0] = make_uint4(lo8[0], lo8[1], lo8[2], lo8[3]);
        pl[1] = make_uint4(lo8[4], lo8[5], lo8[6], lo8[7]);
    };
    auto eplg2 = [&](bool want_fc, float& q0, float& q1) {
        const float* drow = D2 + row*DLD + cb;
        const float* bp   = smf + O_B1/4   + cb;
        const float* f0   = smf + O_FCW0/4 + cb;
        const float* f1   = smf + O_FCW1/4 + cb;
        uint32_t hi8[8], lo8[8];
        q0 = 0.f; q1 = 0.f;
#pragma unroll
        for (int p = 0; p < 8; ++p) {
            float v0 = tanh_fast(drow[2*p]   + bp[2*p]);
            float v1 = tanh_fast(drow[2*p+1] + bp[2*p+1]);
            if (want_fc) {
                q0 += v0*f0[2*p] + v1*f0[2*p+1];
                q1 += v0*f1[2*p] + v1*f1[2*p+1];
            }
            split2(v0, v1, hi8[p], lo8[p]);
        }
        uint4* ph = (uint4*)((char*)h2hi + row*144 + cb*2);
        uint4* pl = (uint4*)((char*)h2lo + row*144 + cb*2);
        ph[0] = make_uint4(hi8[0], hi8[1], hi8[2], hi8[3]);
        ph[1] = make_uint4(hi8[4], hi8[5], hi8[6], hi8[7]);
        pl[0] = make_uint4(lo8[0], lo8[1], lo8[2], lo8[3]);
        pl[1] = make_uint4(lo8[4], lo8[5], lo8[6], lo8[7]);
    };

    // ==================== encoder ====================
    setup_phase(eWhh0, eWih1, eWhh1, eWih0, ebih0, ebhh0, ebih1, ebhh1);
    mma_l0();                                  // D1(0) = h1(=0) @ W0
    __syncthreads();
    eplg1(smf[O_X/4 + row*22], smf[O_X/4 + row*22 + 1]);   // h1(0)
    __syncthreads();
    for (int t = 0; t < T_HIST; ++t) {
        mma_fused(t < T_HIST - 1);             // D2(t) [+ D1(t+1)]
        __syncthreads();
        { float dq0, dq1; eplg2(false, dq0, dq1); }        // h2(t)
        if (t < T_HIST - 1)
            eplg1(smf[O_X/4 + row*22 + 2*(t+1)], smf[O_X/4 + row*22 + 2*(t+1) + 1]);
        __syncthreads();
    }

    // ==================== decoder ====================
    setup_phase(dWhh0, dWih1, dWhh1, dWih0, dbih0, dbhh0, dbih1, dbhh1);
    const float fcb0 = smf[O_FCB/4], fcb1 = smf[O_FCB/4 + 1];
    mma_l0();                                  // D1(d0) = h1(enc) @ dW0
    __syncthreads();
    eplg1(smf[O_X/4 + row*22 + 2*(T_HIST-1)],
          smf[O_X/4 + row*22 + 2*(T_HIST-1) + 1]);         // h1(d0), px = x_last
    __syncthreads();
    for (int t = 0; t < T_PRED; ++t) {
        mma_fused(t < T_PRED - 1);
        __syncthreads();
        float q0, q1;
        eplg2(true, q0, q1);                   // h2(t) + fc partials
        q0 += __shfl_xor_sync(0xffffffffu, q0, 1);
        q1 += __shfl_xor_sync(0xffffffffu, q1, 1);
        q0 += __shfl_xor_sync(0xffffffffu, q0, 2);
        q1 += __shfl_xor_sync(0xffffffffu, q1, 2);
        float px0 = q0 + fcb0, px1 = q1 + fcb1;
        if ((tid & 3) == 0) {
            float* op = out + (size_t)(bg0 + row) * (T_PRED*2) + t*2;
            op[0] = px0; op[1] = px1;
        }
        if (t < T_PRED - 1)
            eplg1(px0, px1);                   // h1(t+1) with pred feedback
        __syncthreads();
    }
}

extern "C" void kernel_launch(void* const* d_in, const int* in_sizes, int n_in,
                              void* d_out, int out_size) {
    (void)in_sizes; (void)n_in; (void)out_size;
    cudaFuncSetAttribute(rnn_wmma_kernel,
                         cudaFuncAttributeMaxDynamicSharedMemorySize, SMEM_TOTAL);
    rnn_wmma_kernel<<<GRID, NTHR, SMEM_TOTAL>>>(
        (const float*)d_in[0],
        (const float*)d_in[1],  (const float*)d_in[2],  (const float*)d_in[3],  (const float*)d_in[4],
        (const float*)d_in[5],  (const float*)d_in[6],  (const float*)d_in[7],  (const float*)d_in[8],
        (const float*)d_in[9],  (const float*)d_in[10], (const float*)d_in[11], (const float*)d_in[12],
        (const float*)d_in[13], (const float*)d_in[14], (const float*)d_in[15], (const float*)d_in[16],
        (const float*)d_in[17], (const float*)d_in[18],
        (float*)d_out);
}

// round 9
// speedup vs baseline: 2.4878x; 1.0148x over previous
#include <cuda_runtime.h>
#include <cuda_bf16.h>
#include <mma.h>
#include <cstdint>

using namespace nvcuda;

static constexpr int NTHR   = 256;   // 2 groups x 4 warps; group = 32 batch rows
static constexpr int BT     = 64;
static constexpr int T_HIST = 11;
static constexpr int T_PRED = 80;
static constexpr int BATCH  = 8192;
static constexpr int GRID   = BATCH / BT;   // 128

// ---- shared memory byte offsets ----
static constexpr int HLD    = 72;            // bf16 leading dim
static constexpr int DLD    = 68;            // fp32 leading dim
static constexpr int O_H1HI = 0;             // 64 x 72 bf16 = 9216 B
static constexpr int O_H1LO = 9216;
static constexpr int O_H2HI = 18432;
static constexpr int O_H2LO = 27648;
static constexpr int O_D1   = 36864;         // 64 x 68 fp32 = 17408 B
static constexpr int O_D2   = 54272;
static constexpr int O_WSTG = 71680;         // staging hi(9216) + lo(9216)
static constexpr int O_X    = 90112;         // 64 x 22 fp32
static constexpr int O_B0   = 95744;
static constexpr int O_B1   = 96000;
static constexpr int O_WX0  = 96256;
static constexpr int O_WX1  = 96512;
static constexpr int O_FCW0 = 96768;
static constexpr int O_FCW1 = 97024;
static constexpr int O_FCB  = 97280;
static constexpr int SMEM_TOTAL = 97296;

typedef wmma::fragment<wmma::matrix_a, 16, 16, 16, __nv_bfloat16, wmma::row_major> AFrag;
typedef wmma::fragment<wmma::matrix_b, 16, 16, 16, __nv_bfloat16, wmma::row_major> BFrag;
typedef wmma::fragment<wmma::accumulator, 16, 16, 16, float> CFrag;

__device__ __forceinline__ float tanh_fast(float x) {
    float t = __expf(2.0f * x);
    return 1.0f - __fdividef(2.0f, t + 1.0f);
}
__device__ __forceinline__ void split2(float f0, float f1, uint32_t& hi, uint32_t& lo) {
    uint32_t u0 = __float_as_uint(f0) & 0xffff0000u;
    uint32_t u1 = __float_as_uint(f1) & 0xffff0000u;
    float l0 = f0 - __uint_as_float(u0);
    float l1 = f1 - __uint_as_float(u1);
    hi = u1 | (u0 >> 16);
    asm("cvt.rn.bf16x2.f32 %0, %1, %2;" : "=r"(lo) : "f"(l1), "f"(l0));
}

__global__ __launch_bounds__(NTHR, 1)
void rnn_wmma_kernel(const float* __restrict__ x,
    const float* __restrict__ eWih0, const float* __restrict__ eWhh0,
    const float* __restrict__ ebih0, const float* __restrict__ ebhh0,
    const float* __restrict__ eWih1, const float* __restrict__ eWhh1,
    const float* __restrict__ ebih1, const float* __restrict__ ebhh1,
    const float* __restrict__ dWih0, const float* __restrict__ dWhh0,
    const float* __restrict__ dbih0, const float* __restrict__ dbhh0,
    const float* __restrict__ dWih1, const float* __restrict__ dWhh1,
    const float* __restrict__ dbih1, const float* __restrict__ dbhh1,
    const float* __restrict__ fcW, const float* __restrict__ fcb,
    float* __restrict__ out)
{
    extern __shared__ __align__(128) char smb[];
    float* smf = (float*)smb;
    const int tid  = threadIdx.x;
    const int wid  = tid >> 5;
    const int g    = tid >> 7;           // pipeline group 0/1 (rows g*32..g*32+31)
    const int gtid = tid & 127;          // thread id within group
    const int nt   = wid & 3;            // n-tile (0..3) within group
    const int row  = g*32 + (gtid >> 2); // epilogue row
    const int cb   = (gtid & 3) * 16;    // epilogue column base
    const int barid = g + 1;             // named barrier id for this group
    const int bg0  = blockIdx.x * BT;

    __nv_bfloat16* h1hi = (__nv_bfloat16*)(smb + O_H1HI);
    __nv_bfloat16* h1lo = (__nv_bfloat16*)(smb + O_H1LO);
    __nv_bfloat16* h2hi = (__nv_bfloat16*)(smb + O_H2HI);
    __nv_bfloat16* h2lo = (__nv_bfloat16*)(smb + O_H2LO);
    __nv_bfloat16* wstg_hi = (__nv_bfloat16*)(smb + O_WSTG);
    __nv_bfloat16* wstg_lo = wstg_hi + 4608;
    float* D1 = smf + O_D1 / 4;
    float* D2 = smf + O_D2 / 4;

    // group barrier: only syncs this group's 128 threads
    auto gbar = [&]() {
        asm volatile("bar.sync %0, 128;" :: "r"(barid) : "memory");
    };

    // persistent weight frags: [0]=W0hi [1]=W0lo [2]=W1hi [3]=W1lo [4]=W2hi [5]=W2lo
    BFrag bW[6][4];

    // ---------------- one-time init ----------------
    for (int i = tid; i < 9216; i += NTHR)
        ((uint32_t*)(smb + O_H1HI))[i] = 0u;
    for (int i = tid; i < BT * 2 * T_HIST; i += NTHR)
        smf[O_X/4 + i] = x[(size_t)bg0 * (2*T_HIST) + i];
    if (tid < 64) { smf[O_FCW0/4 + tid] = fcW[tid]; smf[O_FCW1/4 + tid] = fcW[64 + tid]; }
    if (tid < 2)  { smf[O_FCB/4 + tid] = fcb[tid]; }

    // ---------------- phase setup (shared staging -> full syncthreads) ----------
    auto setup_phase = [&](const float* W0, const float* W1, const float* W2,
                           const float* Wih0, const float* bih0, const float* bhh0,
                           const float* bih1, const float* bhh1) {
        const float* Ws[3] = {W0, W1, W2};
#pragma unroll 1
        for (int w = 0; w < 3; ++w) {
            __syncthreads();
            for (int idx = tid; idx < 4096; idx += NTHR) {
                int k = idx >> 6, j = idx & 63;
                float wv = Ws[w][j*64 + k];           // WT[k][j] = W[j][k]
                uint32_t u = __float_as_uint(wv) & 0xffff0000u;
                unsigned short hb = (unsigned short)(u >> 16);
                __nv_bfloat16 lb = __float2bfloat16(wv - __uint_as_float(u));
                *(unsigned short*)&wstg_hi[k*HLD + j] = hb;
                wstg_lo[k*HLD + j] = lb;
            }
            __syncthreads();
#pragma unroll
            for (int k = 0; k < 4; ++k) {
                wmma::load_matrix_sync(bW[2*w][k],   wstg_hi + k*16*HLD + nt*16, HLD);
                wmma::load_matrix_sync(bW[2*w+1][k], wstg_lo + k*16*HLD + nt*16, HLD);
            }
        }
        if (tid < 64) {
            smf[O_WX0/4 + tid] = Wih0[tid*2];
            smf[O_WX1/4 + tid] = Wih0[tid*2 + 1];
            smf[O_B0/4  + tid] = bih0[tid] + bhh0[tid];
            smf[O_B1/4  + tid] = bih1[tid] + bhh1[tid];
        }
        __syncthreads();
    };

    // ---------------- GEMM phases (group-local: 2 m-tiles of 16 rows) --------
    auto mma_l0 = [&]() {
#pragma unroll
        for (int mi = 0; mi < 2; ++mi) {
            int mrow = g*32 + mi*16;
            CFrag acc; wmma::fill_fragment(acc, 0.0f);
#pragma unroll
            for (int k = 0; k < 4; ++k) {
                AFrag ah, al;
                wmma::load_matrix_sync(ah, h1hi + mrow*HLD + k*16, HLD);
                wmma::load_matrix_sync(al, h1lo + mrow*HLD + k*16, HLD);
                wmma::mma_sync(acc, ah, bW[0][k], acc);
                wmma::mma_sync(acc, ah, bW[1][k], acc);
                wmma::mma_sync(acc, al, bW[0][k], acc);
            }
            wmma::store_matrix_sync(D1 + mrow*DLD + nt*16, acc, DLD, wmma::mem_row_major);
        }
    };
    auto mma_fused = [&](bool with_l0) {
#pragma unroll
        for (int mi = 0; mi < 2; ++mi) {
            int mrow = g*32 + mi*16;
            CFrag acc2; wmma::fill_fragment(acc2, 0.0f);
            CFrag acc1; wmma::fill_fragment(acc1, 0.0f);
#pragma unroll
            for (int k = 0; k < 4; ++k) {
                AFrag a1h, a1l, a2h, a2l;
                wmma::load_matrix_sync(a1h, h1hi + mrow*HLD + k*16, HLD);
                wmma::load_matrix_sync(a1l, h1lo + mrow*HLD + k*16, HLD);
                wmma::load_matrix_sync(a2h, h2hi + mrow*HLD + k*16, HLD);
                wmma::load_matrix_sync(a2l, h2lo + mrow*HLD + k*16, HLD);
                wmma::mma_sync(acc2, a1h, bW[2][k], acc2);
                wmma::mma_sync(acc2, a1h, bW[3][k], acc2);
                wmma::mma_sync(acc2, a1l, bW[2][k], acc2);
                wmma::mma_sync(acc2, a2h, bW[4][k], acc2);
                wmma::mma_sync(acc2, a2h, bW[5][k], acc2);
                wmma::mma_sync(acc2, a2l, bW[4][k], acc2);
                if (with_l0) {
                    wmma::mma_sync(acc1, a1h, bW[0][k], acc1);
                    wmma::mma_sync(acc1, a1h, bW[1][k], acc1);
                    wmma::mma_sync(acc1, a1l, bW[0][k], acc1);
                }
            }
            wmma::store_matrix_sync(D2 + mrow*DLD + nt*16, acc2, DLD, wmma::mem_row_major);
            if (with_l0)
                wmma::store_matrix_sync(D1 + mrow*DLD + nt*16, acc1, DLD, wmma::mem_row_major);
        }
    };

    // ---------------- epilogues (thread-local) ----------------
    auto eplg1 = [&](float x0, float x1) {
        const float* drow = D1 + row*DLD + cb;
        const float* bp   = smf + O_B0/4  + cb;
        const float* w0p  = smf + O_WX0/4 + cb;
        const float* w1p  = smf + O_WX1/4 + cb;
        uint32_t hi8[8], lo8[8];
#pragma unroll
        for (int p = 0; p < 8; ++p) {
            float v0 = tanh_fast(drow[2*p]   + bp[2*p]   + x0*w0p[2*p]   + x1*w1p[2*p]);
            float v1 = tanh_fast(drow[2*p+1] + bp[2*p+1] + x0*w0p[2*p+1] + x1*w1p[2*p+1]);
            split2(v0, v1, hi8[p], lo8[p]);
        }
        uint4* ph = (uint4*)((char*)h1hi + row*144 + cb*2);
        uint4* pl = (uint4*)((char*)h1lo + row*144 + cb*2);
        ph[0] = make_uint4(hi8[0], hi8[1], hi8[2], hi8[3]);
        ph[1] = make_uint4(hi8[4], hi8[5], hi8[6], hi8[7]);
        pl[0] = make_uint4(lo8[0], lo8[1], lo8[2], lo8[3]);
        pl[1] = make_uint4(lo8[4], lo8[5], lo8[6], lo8[7]);
    };
    auto eplg2 = [&](bool want_fc, float& q0, float& q1) {
        const float* drow = D2 + row*DLD + cb;
        const float* bp   = smf + O_B1/4   + cb;
        const float* f0   = smf + O_FCW0/4 + cb;
        const float* f1   = smf + O_FCW1/4 + cb;
        uint32_t hi8[8], lo8[8];
        q0 = 0.f; q1 = 0.f;
#pragma unroll
        for (int p = 0; p < 8; ++p) {
            float v0 = tanh_fast(drow[2*p]   + bp[2*p]);
            float v1 = tanh_fast(drow[2*p+1] + bp[2*p+1]);
            if (want_fc) {
                q0 += v0*f0[2*p] + v1*f0[2*p+1];
                q1 += v0*f1[2*p] + v1*f1[2*p+1];
            }
            split2(v0, v1, hi8[p], lo8[p]);
        }
        uint4* ph = (uint4*)((char*)h2hi + row*144 + cb*2);
        uint4* pl = (uint4*)((char*)h2lo + row*144 + cb*2);
        ph[0] = make_uint4(hi8[0], hi8[1], hi8[2], hi8[3]);
        ph[1] = make_uint4(hi8[4], hi8[5], hi8[6], hi8[7]);
        pl[0] = make_uint4(lo8[0], lo8[1], lo8[2], lo8[3]);
        pl[1] = make_uint4(lo8[4], lo8[5], lo8[6], lo8[7]);
    };

    // ==================== encoder ====================
    setup_phase(eWhh0, eWih1, eWhh1, eWih0, ebih0, ebhh0, ebih1, ebhh1);
    mma_l0();
    gbar();
    eplg1(smf[O_X/4 + row*22], smf[O_X/4 + row*22 + 1]);
    gbar();
    for (int t = 0; t < T_HIST; ++t) {
        mma_fused(t < T_HIST - 1);
        gbar();
        { float dq0, dq1; eplg2(false, dq0, dq1); }
        if (t < T_HIST - 1)
            eplg1(smf[O_X/4 + row*22 + 2*(t+1)], smf[O_X/4 + row*22 + 2*(t+1) + 1]);
        gbar();
    }

    // ==================== decoder ====================
    setup_phase(dWhh0, dWih1, dWhh1, dWih0, dbih0, dbhh0, dbih1, dbhh1);
    const float fcb0 = smf[O_FCB/4], fcb1 = smf[O_FCB/4 + 1];
    mma_l0();
    gbar();
    eplg1(smf[O_X/4 + row*22 + 2*(T_HIST-1)],
          smf[O_X/4 + row*22 + 2*(T_HIST-1) + 1]);
    gbar();
    for (int t = 0; t < T_PRED; ++t) {
        mma_fused(t < T_PRED - 1);
        gbar();
        float q0, q1;
        eplg2(true, q0, q1);
        q0 += __shfl_xor_sync(0xffffffffu, q0, 1);
        q1 += __shfl_xor_sync(0xffffffffu, q1, 1);
        q0 += __shfl_xor_sync(0xffffffffu, q0, 2);
        q1 += __shfl_xor_sync(0xffffffffu, q1, 2);
        float px0 = q0 + fcb0, px1 = q1 + fcb1;
        if ((gtid & 3) == 0) {
            float* op = out + (size_t)(bg0 + row) * (T_PRED*2) + t*2;
            op[0] = px0; op[1] = px1;
        }
        if (t < T_PRED - 1)
            eplg1(px0, px1);
        gbar();
    }
}

extern "C" void kernel_launch(void* const* d_in, const int* in_sizes, int n_in,
                              void* d_out, int out_size) {
    (void)in_sizes; (void)n_in; (void)out_size;
    cudaFuncSetAttribute(rnn_wmma_kernel,
                         cudaFuncAttributeMaxDynamicSharedMemorySize, SMEM_TOTAL);
    rnn_wmma_kernel<<<GRID, NTHR, SMEM_TOTAL>>>(
        (const float*)d_in[0],
        (const float*)d_in[1],  (const float*)d_in[2],  (const float*)d_in[3],  (const float*)d_in[4],
        (const float*)d_in[5],  (const float*)d_in[6],  (const float*)d_in[7],  (const float*)d_in[8],
        (const float*)d_in[9],  (const float*)d_in[10], (const float*)d_in[11], (const float*)d_in[12],
        (const float*)d_in[13], (const float*)d_in[14], (const float*)d_in[15], (const float*)d_in[16],
        (const float*)d_in[17], (const float*)d_in[18],
        (float*)d_out);
}

// round 10
// speedup vs baseline: 3.5402x; 1.4230x over previous
#include <cuda_runtime.h>
#include <cuda_bf16.h>
#include <cstdint>

static constexpr int NTHR = 256;     // 8 warps: nt = wid&3 (16-col group), mh = wid>>2 (32-row group)
static constexpr int BT = 64;
static constexpr int T_HIST = 11, T_PRED = 80, BATCH = 8192;
static constexpr int GRID = BATCH / BT;   // 128

// ---- smem byte offsets ----
static constexpr int HB     = 9216;       // one 64x72 bf16 buffer (144B rows)
static constexpr int O_H1HI = 0;          // 2 buffers each
static constexpr int O_H1LO = 18432;
static constexpr int O_H2HI = 36864;
static constexpr int O_H2LO = 55296;
static constexpr int O_WSTG = 73728;      // staging: hi 9216 + lo 9216
static constexpr int O_X    = 92160;      // 64 x 22 fp32
static constexpr int O_B0   = 97792;
static constexpr int O_B1   = 98048;
static constexpr int O_WX0  = 98304;
static constexpr int O_WX1  = 98560;
static constexpr int O_FCW0 = 98816;
static constexpr int O_FCW1 = 99072;
static constexpr int O_FCB  = 99328;
static constexpr int O_PART = 99344;      // 64 rows x 8 floats
static constexpr int SMEM_TOTAL = 101392;

__device__ __forceinline__ uint32_t smem_u32(const void* p) {
    uint32_t a;
    asm("{\n\t.reg .u64 t;\n\tcvta.to.shared.u64 t, %1;\n\tcvt.u32.u64 %0, t;\n\t}"
        : "=r"(a) : "l"(p));
    return a;
}
__device__ __forceinline__ void ldsm4(uint32_t r[4], uint32_t a) {
    asm volatile("ldmatrix.sync.aligned.m8n8.x4.shared.b16 {%0,%1,%2,%3}, [%4];"
        : "=r"(r[0]), "=r"(r[1]), "=r"(r[2]), "=r"(r[3]) : "r"(a));
}
__device__ __forceinline__ void mma_bf16(float c[4], const uint32_t a[4], const uint32_t b[2]) {
    asm volatile(
        "mma.sync.aligned.m16n8k16.row.col.f32.bf16.bf16.f32 "
        "{%0,%1,%2,%3},{%4,%5,%6,%7},{%8,%9},{%0,%1,%2,%3};"
        : "+f"(c[0]), "+f"(c[1]), "+f"(c[2]), "+f"(c[3])
        : "r"(a[0]), "r"(a[1]), "r"(a[2]), "r"(a[3]), "r"(b[0]), "r"(b[1]));
}
__device__ __forceinline__ float tanh_fast(float x) {
    float t = __expf(2.0f * x);
    return 1.0f - __fdividef(2.0f, t + 1.0f);
}
__device__ __forceinline__ void split2(float f0, float f1, uint32_t& hi, uint32_t& lo) {
    uint32_t u0 = __float_as_uint(f0) & 0xffff0000u;
    uint32_t u1 = __float_as_uint(f1) & 0xffff0000u;
    float l0 = f0 - __uint_as_float(u0);
    float l1 = f1 - __uint_as_float(u1);
    hi = u1 | (u0 >> 16);
    asm("cvt.rn.bf16x2.f32 %0, %1, %2;" : "=r"(lo) : "f"(l1), "f"(l0));
}

__global__ __launch_bounds__(NTHR, 1)
void rnn_mma_kernel(const float* __restrict__ x,
    const float* __restrict__ eWih0, const float* __restrict__ eWhh0,
    const float* __restrict__ ebih0, const float* __restrict__ ebhh0,
    const float* __restrict__ eWih1, const float* __restrict__ eWhh1,
    const float* __restrict__ ebih1, const float* __restrict__ ebhh1,
    const float* __restrict__ dWih0, const float* __restrict__ dWhh0,
    const float* __restrict__ dbih0, const float* __restrict__ dbhh0,
    const float* __restrict__ dWih1, const float* __restrict__ dWhh1,
    const float* __restrict__ dbih1, const float* __restrict__ dbhh1,
    const float* __restrict__ fcW, const float* __restrict__ fcb,
    float* __restrict__ out)
{
    extern __shared__ __align__(128) char smb[];
    float* smf = (float*)smb;
    const uint32_t sb = smem_u32(smb);
    const int tid  = threadIdx.x;
    const int wid  = tid >> 5, lane = tid & 31;
    const int nt   = wid & 3;            // col group: cols nt*16 .. +15
    const int mh   = wid >> 2;           // row group: rows mh*32 .. +31
    const int ln4  = lane >> 2, lm4 = lane & 3;
    const int barid = mh + 1;
    const int bg0  = blockIdx.x * BT;
    const uint32_t a_off = (uint32_t)((lane & 15) * 144 + (lane >> 4) * 16);

    auto gbar = [&]() { asm volatile("bar.sync %0, 128;" :: "r"(barid) : "memory"); };

    // persistent B frags: [0]=W0hi [1]=W0lo [2]=W1hi [3]=W1lo [4]=W2hi [5]=W2lo
    uint32_t bW[6][4][2][2];
    // accumulators + scratch (captured by lambdas)
    float aL1[2][2][4], aL0[2][2][4];
    float q0v[4], q1v[4], p0v[4], p1v[4];

    auto zero_acc = [&]() {
#pragma unroll
        for (int mi = 0; mi < 2; ++mi)
#pragma unroll
        for (int nj = 0; nj < 2; ++nj)
#pragma unroll
        for (int e = 0; e < 4; ++e) { aL1[mi][nj][e] = 0.f; aL0[mi][nj][e] = 0.f; }
    };

    // ---------------- one-time init ----------------
    for (int i = tid; i < 18432; i += NTHR) ((uint32_t*)smb)[i] = 0u;   // zero all h buffers
    for (int i = tid; i < BT * 2 * T_HIST; i += NTHR)
        smf[O_X/4 + i] = x[(size_t)bg0 * (2*T_HIST) + i];
    if (tid < 64) { smf[O_FCW0/4 + tid] = fcW[tid]; smf[O_FCW1/4 + tid] = fcW[64 + tid]; }
    if (tid < 2)  { smf[O_FCB/4 + tid] = fcb[tid]; }

    // ---------------- phase setup ----------------
    auto setup_phase = [&](const float* W0, const float* W1, const float* W2,
                           const float* Wih0, const float* bih0, const float* bhh0,
                           const float* bih1, const float* bhh1) {
        const float* Ws[3] = {W0, W1, W2};
        unsigned short* sh = (unsigned short*)(smb + O_WSTG);
        unsigned short* sl = sh + 4608;
#pragma unroll
        for (int w = 0; w < 3; ++w) {
            __syncthreads();
            for (int idx = tid; idx < 4096; idx += NTHR) {
                int k = idx >> 6, j = idx & 63;
                float wv = Ws[w][j*64 + k];            // WT[k][j] = W[j][k]
                uint32_t u = __float_as_uint(wv) & 0xffff0000u;
                __nv_bfloat16 lb = __float2bfloat16(wv - __uint_as_float(u));
                sh[k*72 + j] = (unsigned short)(u >> 16);
                sl[k*72 + j] = *(unsigned short*)&lb;
            }
            __syncthreads();
            int n  = nt*16 + ln4;       // + nj*8 below
#pragma unroll
            for (int kc = 0; kc < 4; ++kc)
#pragma unroll
            for (int nj = 0; nj < 2; ++nj) {
                int nn = n + nj*8;
                int k0 = kc*16 + lm4*2;
                bW[2*w][kc][nj][0]   = (uint32_t)sh[k0*72+nn]     | ((uint32_t)sh[(k0+1)*72+nn] << 16);
                bW[2*w][kc][nj][1]   = (uint32_t)sh[(k0+8)*72+nn] | ((uint32_t)sh[(k0+9)*72+nn] << 16);
                bW[2*w+1][kc][nj][0] = (uint32_t)sl[k0*72+nn]     | ((uint32_t)sl[(k0+1)*72+nn] << 16);
                bW[2*w+1][kc][nj][1] = (uint32_t)sl[(k0+8)*72+nn] | ((uint32_t)sl[(k0+9)*72+nn] << 16);
            }
        }
        if (tid < 64) {
            smf[O_WX0/4 + tid] = Wih0[tid*2];
            smf[O_WX1/4 + tid] = Wih0[tid*2 + 1];
            smf[O_B0/4  + tid] = bih0[tid] + bhh0[tid];
            smf[O_B1/4  + tid] = bih1[tid] + bhh1[tid];
        }
        __syncthreads();
    };

    // ---------------- MMA phases ----------------
    auto run_mma = [&](int b1, int b2, bool with_l0) {
        const uint32_t h1h = sb + O_H1HI + b1*HB;
        const uint32_t h1l = sb + O_H1LO + b1*HB;
        const uint32_t h2h = sb + O_H2HI + b2*HB;
        const uint32_t h2l = sb + O_H2LO + b2*HB;
#pragma unroll
        for (int kc = 0; kc < 4; ++kc)
#pragma unroll
        for (int mi = 0; mi < 2; ++mi) {
            uint32_t base = (uint32_t)((mh*32 + mi*16) * 144 + kc*32) + a_off;
            uint32_t A1h[4], A1l[4], A2h[4], A2l[4];
            ldsm4(A1h, h1h + base); ldsm4(A1l, h1l + base);
            ldsm4(A2h, h2h + base); ldsm4(A2l, h2l + base);
#pragma unroll
            for (int nj = 0; nj < 2; ++nj) {
                mma_bf16(aL1[mi][nj], A1h, bW[2][kc][nj]);
                mma_bf16(aL1[mi][nj], A1h, bW[3][kc][nj]);
                mma_bf16(aL1[mi][nj], A1l, bW[2][kc][nj]);
                mma_bf16(aL1[mi][nj], A2h, bW[4][kc][nj]);
                mma_bf16(aL1[mi][nj], A2h, bW[5][kc][nj]);
                mma_bf16(aL1[mi][nj], A2l, bW[4][kc][nj]);
                if (with_l0) {
                    mma_bf16(aL0[mi][nj], A1h, bW[0][kc][nj]);
                    mma_bf16(aL0[mi][nj], A1h, bW[1][kc][nj]);
                    mma_bf16(aL0[mi][nj], A1l, bW[0][kc][nj]);
                }
            }
        }
    };
    auto run_l0 = [&](int b1) {
        const uint32_t h1h = sb + O_H1HI + b1*HB;
        const uint32_t h1l = sb + O_H1LO + b1*HB;
#pragma unroll
        for (int kc = 0; kc < 4; ++kc)
#pragma unroll
        for (int mi = 0; mi < 2; ++mi) {
            uint32_t base = (uint32_t)((mh*32 + mi*16) * 144 + kc*32) + a_off;
            uint32_t A1h[4], A1l[4];
            ldsm4(A1h, h1h + base); ldsm4(A1l, h1l + base);
#pragma unroll
            for (int nj = 0; nj < 2; ++nj) {
                mma_bf16(aL0[mi][nj], A1h, bW[0][kc][nj]);
                mma_bf16(aL0[mi][nj], A1h, bW[1][kc][nj]);
                mma_bf16(aL0[mi][nj], A1l, bW[0][kc][nj]);
            }
        }
    };

    // ---------------- epilogues (acc-register layout) ----------------
    // acc elem map: c0=(r,c) c1=(r,c+1) c2=(r+8,c) c3=(r+8,c+1); r=tilerow+ln4, c=tilecol+lm4*2
    auto eplg2 = [&](bool want_fc, int bufn) {
        char* d_hi = smb + O_H2HI + bufn*HB;
        char* d_lo = smb + O_H2LO + bufn*HB;
#pragma unroll
        for (int i = 0; i < 4; ++i) { q0v[i] = 0.f; q1v[i] = 0.f; }
#pragma unroll
        for (int mi = 0; mi < 2; ++mi)
#pragma unroll
        for (int nj = 0; nj < 2; ++nj) {
            int c = nt*16 + nj*8 + lm4*2;
            float2 bb = *(const float2*)(smf + O_B1/4 + c);
            const float* a = aL1[mi][nj];
            float v0 = tanh_fast(a[0] + bb.x), v1 = tanh_fast(a[1] + bb.y);
            float v2 = tanh_fast(a[2] + bb.x), v3 = tanh_fast(a[3] + bb.y);
            if (want_fc) {
                float2 f0 = *(const float2*)(smf + O_FCW0/4 + c);
                float2 f1 = *(const float2*)(smf + O_FCW1/4 + c);
                q0v[mi*2+0] += v0*f0.x + v1*f0.y;  q1v[mi*2+0] += v0*f1.x + v1*f1.y;
                q0v[mi*2+1] += v2*f0.x + v3*f0.y;  q1v[mi*2+1] += v2*f1.x + v3*f1.y;
            }
            uint32_t hi0, lo0, hi1, lo1;
            split2(v0, v1, hi0, lo0); split2(v2, v3, hi1, lo1);
            int r0 = mh*32 + mi*16 + ln4;
            *(uint32_t*)(d_hi + r0*144 + c*2)       = hi0;
            *(uint32_t*)(d_lo + r0*144 + c*2)       = lo0;
            *(uint32_t*)(d_hi + (r0+8)*144 + c*2)   = hi1;
            *(uint32_t*)(d_lo + (r0+8)*144 + c*2)   = lo1;
        }
        if (want_fc) {
#pragma unroll
            for (int i = 0; i < 4; ++i) {
                q0v[i] += __shfl_xor_sync(0xffffffffu, q0v[i], 1);
                q0v[i] += __shfl_xor_sync(0xffffffffu, q0v[i], 2);
                q1v[i] += __shfl_xor_sync(0xffffffffu, q1v[i], 1);
                q1v[i] += __shfl_xor_sync(0xffffffffu, q1v[i], 2);
            }
            if (lm4 == 0) {
#pragma unroll
                for (int i = 0; i < 4; ++i) {
                    int row = mh*32 + (i>>1)*16 + (i&1)*8 + ln4;
                    *(float2*)(smb + O_PART + row*32 + nt*8) = make_float2(q0v[i], q1v[i]);
                }
            }
        }
    };
    auto eplg1 = [&](int bufn) {   // uses p0v/p1v per-row inputs
        char* d_hi = smb + O_H1HI + bufn*HB;
        char* d_lo = smb + O_H1LO + bufn*HB;
#pragma unroll
        for (int mi = 0; mi < 2; ++mi)
#pragma unroll
        for (int nj = 0; nj < 2; ++nj) {
            int c = nt*16 + nj*8 + lm4*2;
            float2 bb = *(const float2*)(smf + O_B0/4 + c);
            float2 w0 = *(const float2*)(smf + O_WX0/4 + c);
            float2 w1 = *(const float2*)(smf + O_WX1/4 + c);
            const float* a = aL0[mi][nj];
            float pA0 = p0v[mi*2+0], pA1 = p1v[mi*2+0];
            float pB0 = p0v[mi*2+1], pB1 = p1v[mi*2+1];
            float v0 = tanh_fast(a[0] + bb.x + pA0*w0.x + pA1*w1.x);
            float v1 = tanh_fast(a[1] + bb.y + pA0*w0.y + pA1*w1.y);
            float v2 = tanh_fast(a[2] + bb.x + pB0*w0.x + pB1*w1.x);
            float v3 = tanh_fast(a[3] + bb.y + pB0*w0.y + pB1*w1.y);
            uint32_t hi0, lo0, hi1, lo1;
            split2(v0, v1, hi0, lo0); split2(v2, v3, hi1, lo1);
            int r0 = mh*32 + mi*16 + ln4;
            *(uint32_t*)(d_hi + r0*144 + c*2)       = hi0;
            *(uint32_t*)(d_lo + r0*144 + c*2)       = lo0;
            *(uint32_t*)(d_hi + (r0+8)*144 + c*2)   = hi1;
            *(uint32_t*)(d_lo + (r0+8)*144 + c*2)   = lo1;
        }
    };
    auto load_x = [&](int t) {
#pragma unroll
        for (int i = 0; i < 4; ++i) {
            int row = mh*32 + (i>>1)*16 + (i&1)*8 + ln4;
            float2 xv = *(const float2*)(smf + O_X/4 + row*22 + 2*t);
            p0v[i] = xv.x; p1v[i] = xv.y;
        }
    };

    // ==================== encoder ====================
    setup_phase(eWhh0, eWih1, eWhh1, eWih0, ebih0, ebhh0, ebih1, ebhh1);
    int c1 = 0, c2 = 0;
    zero_acc();
    load_x(0);
    eplg1(c1);                 // h1(0) into buf0 (l0 acc = 0)
    gbar();
    for (int t = 0; t < T_HIST; ++t) {
        zero_acc();
        run_mma(c1, c2, t < T_HIST - 1);
        eplg2(false, c2 ^ 1);
        if (t < T_HIST - 1) { load_x(t + 1); eplg1(c1 ^ 1); c1 ^= 1; }
        c2 ^= 1;
        gbar();
    }

    // ==================== decoder ====================
    setup_phase(dWhh0, dWih1, dWhh1, dWih0, dbih0, dbhh0, dbih1, dbhh1);
    const float fcb0 = smf[O_FCB/4], fcb1 = smf[O_FCB/4 + 1];
    zero_acc();
    run_l0(c1);                // h1_enc @ dW0
    load_x(T_HIST - 1);        // px = x[:, -1, :]
    eplg1(c1 ^ 1); c1 ^= 1;
    gbar();
    for (int t = 0; t < T_PRED; ++t) {
        zero_acc();
        run_mma(c1, c2, t < T_PRED - 1);
        eplg2(true, c2 ^ 1);
        gbar();
        // finish pred(t): reduce partials per row
#pragma unroll
        for (int i = 0; i < 4; ++i) {
            int row = mh*32 + (i>>1)*16 + (i&1)*8 + ln4;
            float4 pa = *(const float4*)(smb + O_PART + row*32);
            float4 pb = *(const float4*)(smb + O_PART + row*32 + 16);
            p0v[i] = fcb0 + pa.x + pa.z + pb.x + pb.z;
            p1v[i] = fcb1 + pa.y + pa.w + pb.y + pb.w;
        }
        if (nt == 0 && lm4 == 0) {
#pragma unroll
            for (int i = 0; i < 4; ++i) {
                int row = mh*32 + (i>>1)*16 + (i&1)*8 + ln4;
                float* op = out + (size_t)(bg0 + row) * (T_PRED*2) + t*2;
                op[0] = p0v[i]; op[1] = p1v[i];
            }
        }
        if (t < T_PRED - 1) { eplg1(c1 ^ 1); c1 ^= 1; }
        c2 ^= 1;
        gbar();
    }
}

extern "C" void kernel_launch(void* const* d_in, const int* in_sizes, int n_in,
                              void* d_out, int out_size) {
    (void)in_sizes; (void)n_in; (void)out_size;
    cudaFuncSetAttribute(rnn_mma_kernel,
                         cudaFuncAttributeMaxDynamicSharedMemorySize, SMEM_TOTAL);
    rnn_mma_kernel<<<GRID, NTHR, SMEM_TOTAL>>>(
        (const float*)d_in[0],
        (const float*)d_in[1],  (const float*)d_in[2],  (const float*)d_in[3],  (const float*)d_in[4],
        (const float*)d_in[5],  (const float*)d_in[6],  (const float*)d_in[7],  (const float*)d_in[8],
        (const float*)d_in[9],  (const float*)d_in[10], (const float*)d_in[11], (const float*)d_in[12],
        (const float*)d_in[13], (const float*)d_in[14], (const float*)d_in[15], (const float*)d_in[16],
        (const float*)d_in[17], (const float*)d_in[18],
        (float*)d_out);
}